// round 8
// baseline (speedup 1.0000x reference)
#include <cuda_runtime.h>
#include <cuda_fp16.h>
#include <stdint.h>
#include <math.h>

static constexpr int Bc = 2;
static constexpr int Nc = 16384;
static constexpr int Kc = 16;

// ---------------- scratch ----------------
__device__ __half g_fT[(size_t)Bc * Nc * 128];   // features transposed [b][n][c]
__device__ __half g_wh[311296];                  // all conv weights as fp16
__device__ __half g_x1[(size_t)Bc * Nc * 128];   // mlp1 out  [b][n][c]
__device__ __half g_m1[(size_t)Bc * Nc * 256];   // lse1 pooled mean
__device__ __half g_p1[(size_t)Bc * Nc * 128];   // pool1 pre-GN
__device__ __half g_m2[(size_t)Bc * Nc * 256];   // lse2 pooled mean
__device__ __half g_p2[(size_t)Bc * Nc * 256];   // pool2 pre-GN
__device__ __half g_x3[(size_t)Bc * Nc * 256];   // pool2 out
__device__ __half g_scp[(size_t)Bc * Nc * 512];  // shortcut pre-GN, [b][o][n] fp16

__device__ double g_geoS[Bc * 10];
__device__ double g_geoG[Bc * 55];
__device__ float g_lse1a[Bc * 128], g_lse1c[Bc * 128];
__device__ float g_lse2a[Bc * 128], g_lse2c[Bc * 128];
__device__ float g_p1s[Bc * 16], g_p1q[Bc * 16];
__device__ float g_p2s[Bc * 16], g_p2q[Bc * 16];
__device__ float g_scs[Bc * 16], g_scq[Bc * 16];
__device__ float g_pa1[Bc * 128], g_pc1[Bc * 128];
__device__ float g_pa2[Bc * 256], g_pc2[Bc * 256];
__device__ float g_sca[Bc * 512], g_scc[Bc * 512];

// weight blob offsets (in halves)
static constexpr int WOFF_W1 = 0;
static constexpr int WOFF_P1 = 16384;
static constexpr int WOFF_P2 = 49152;
static constexpr int WOFF_SC = 114688;
static constexpr int WOFF_M2 = 180224;
static constexpr int WTOT = 311296;

// ---------------- helpers ----------------
__device__ __forceinline__ uint32_t smem_u32(const void* p) {
    uint32_t a;
    asm("{ .reg .u64 t; cvta.to.shared.u64 t, %1; cvt.u32.u64 %0, t; }" : "=r"(a) : "l"(p));
    return a;
}
__device__ __forceinline__ void cpa16(uint32_t dst, const void* src) {
    asm volatile("cp.async.cg.shared.global [%0], [%1], 16;" :: "r"(dst), "l"(src));
}
#define CP_COMMIT() asm volatile("cp.async.commit_group;" ::: "memory")
#define CP_WAIT1() asm volatile("cp.async.wait_group 1;" ::: "memory")
#define CP_WAIT0() asm volatile("cp.async.wait_group 0;" ::: "memory")

#define MMA_F16(d, a, b) \
    asm volatile("mma.sync.aligned.m16n8k16.row.col.f32.f16.f16.f32 " \
        "{%0,%1,%2,%3}, {%4,%5,%6,%7}, {%8,%9}, {%0,%1,%2,%3};" \
        : "+f"((d)[0]), "+f"((d)[1]), "+f"((d)[2]), "+f"((d)[3]) \
        : "r"((a)[0]), "r"((a)[1]), "r"((a)[2]), "r"((a)[3]), \
          "r"((b)[0]), "r"((b)[1]))

#define LDSM4(r, addr) \
    asm volatile("ldmatrix.sync.aligned.m8n8.x4.shared.b16 {%0,%1,%2,%3}, [%4];" \
        : "=r"((r)[0]), "=r"((r)[1]), "=r"((r)[2]), "=r"((r)[3]) : "r"(addr))

// swizzled offset within a row-major 128B-row tile: row r, 16B-chunk c (0..7)
__device__ __forceinline__ uint32_t swoff(int r, int c) {
    return (uint32_t)(r * 128 + ((c ^ (r & 7)) << 4));
}

// ---------------- prep: zero stats + convert weights to fp16 ----------------
__global__ __launch_bounds__(256) void prep_kernel(
    const float* __restrict__ w1, const float* __restrict__ pw1,
    const float* __restrict__ pw2, const float* __restrict__ scw,
    const float* __restrict__ mw)
{
    if (blockIdx.x == 0) {
        int t = threadIdx.x;
        if (t < Bc * 10) g_geoS[t] = 0.0;
        if (t < Bc * 55) g_geoG[t] = 0.0;
        if (t < Bc * 16) {
            g_p1s[t] = 0.f; g_p1q[t] = 0.f;
            g_p2s[t] = 0.f; g_p2q[t] = 0.f;
            g_scs[t] = 0.f; g_scq[t] = 0.f;
        }
    }
    for (int i = blockIdx.x * blockDim.x + threadIdx.x; i < WTOT;
         i += gridDim.x * blockDim.x) {
        float v;
        if (i < WOFF_P1) v = w1[i];
        else if (i < WOFF_P2) v = pw1[i - WOFF_P1];
        else if (i < WOFF_SC) v = pw2[i - WOFF_P2];
        else if (i < WOFF_M2) v = scw[i - WOFF_SC];
        else v = mw[i - WOFF_M2];
        g_wh[i] = __float2half(v);
    }
}

// ---------------- transpose features [b][c][n] fp32 -> [b][n][c] fp16 -------
__global__ __launch_bounds__(256) void transpose_f16_kernel(
    const float* __restrict__ in, __half* __restrict__ outp)
{
    __shared__ float t[32][33];
    int b = blockIdx.z;
    int cB = blockIdx.y * 32, nB = blockIdx.x * 32;
    int tx = threadIdx.x & 31, ty = threadIdx.x >> 5;
#pragma unroll
    for (int i = 0; i < 4; ++i)
        t[ty + 8 * i][tx] = in[((size_t)b * 128 + cB + ty + 8 * i) * Nc + nB + tx];
    __syncthreads();
#pragma unroll
    for (int i = 0; i < 4; ++i)
        outp[((size_t)b * Nc + nB + ty + 8 * i) * 128 + cB + tx] =
            __float2half(t[tx][ty + 8 * i]);
}

// ---------------- geo moments ----------------
__global__ __launch_bounds__(256) void geo_moments_kernel(
    const float* __restrict__ coords, const int* __restrict__ knn_idx,
    const float* __restrict__ knn_dist)
{
    const int b = blockIdx.y;
    const float* cb = coords + (size_t)b * Nc * 3;
    float S[10];
    float G[55];
#pragma unroll
    for (int c = 0; c < 10; c++) S[c] = 0.f;
#pragma unroll
    for (int p = 0; p < 55; p++) G[p] = 0.f;

    for (int it = blockIdx.x * blockDim.x + threadIdx.x; it < Nc * Kc;
         it += gridDim.x * blockDim.x) {
        int n = it >> 4;
        size_t base = ((size_t)b * Nc + n) * Kc + (it & 15);
        float cx = cb[n * 3 + 0], cy = cb[n * 3 + 1], cz = cb[n * 3 + 2];
        int j = knn_idx[base];
        float nx = cb[j * 3 + 0], ny = cb[j * 3 + 1], nz = cb[j * 3 + 2];
        float dd = knn_dist[base];
        float g[10] = {cx, cy, cz, nx, ny, nz, cx - nx, cy - ny, cz - nz, dd};
        int p = 0;
#pragma unroll
        for (int c = 0; c < 10; c++) {
            S[c] += g[c];
#pragma unroll
            for (int d = c; d < 10; d++) G[p++] += g[c] * g[d];
        }
    }
#pragma unroll
    for (int c = 0; c < 10; c++)
        for (int off = 16; off; off >>= 1) S[c] += __shfl_xor_sync(~0u, S[c], off);
#pragma unroll
    for (int p = 0; p < 55; p++)
        for (int off = 16; off; off >>= 1) G[p] += __shfl_xor_sync(~0u, G[p], off);
    if ((threadIdx.x & 31) == 0) {
        for (int c = 0; c < 10; c++) atomicAdd(&g_geoS[b * 10 + c], (double)S[c]);
        for (int p = 0; p < 55; p++) atomicAdd(&g_geoG[b * 55 + p], (double)G[p]);
    }
}

// ---------------- closed-form GN stats for BOTH LSE layers -----------------
__global__ void lse_finalize_kernel(
    const float* __restrict__ w1p, const float* __restrict__ b1p,
    const float* __restrict__ gw1, const float* __restrict__ gb1,
    const float* __restrict__ w2p, const float* __restrict__ b2p,
    const float* __restrict__ gw2, const float* __restrict__ gb2,
    float* __restrict__ a1o, float* __restrict__ c1o,
    float* __restrict__ a2o, float* __restrict__ c2o)
{
    int b = blockIdx.x;
    int layer = blockIdx.y;
    const float* w = layer ? w2p : w1p;
    const float* bias = layer ? b2p : b1p;
    const float* gw = layer ? gw2 : gw1;
    const float* gb = layer ? gb2 : gb1;
    float* aOut = layer ? a2o : a1o;
    float* cOut = layer ? c2o : c1o;

    int o = threadIdx.x;  // 128
    float wr[10];
#pragma unroll
    for (int c = 0; c < 10; c++) wr[c] = w[o * 10 + c];
    double t1 = 0.0;
#pragma unroll
    for (int c = 0; c < 10; c++) t1 += (double)wr[c] * g_geoS[b * 10 + c];
    double t2 = 0.0;
    int p = 0;
#pragma unroll
    for (int c = 0; c < 10; c++)
#pragma unroll
        for (int d = c; d < 10; d++) {
            double gv = g_geoG[b * 55 + p]; p++;
            double ww = (double)wr[c] * (double)wr[d];
            t2 += (c == d ? ww : 2.0 * ww) * gv;
        }
    double NK = (double)Nc * (double)Kc;
    double bo = (double)bias[o];
    double sum = t1 + bo * NK;
    double sq  = t2 + 2.0 * bo * t1 + bo * bo * NK;

    __shared__ double gs[16], gq[16];
    if (o < 16) { gs[o] = 0.0; gq[o] = 0.0; }
    __syncthreads();
    atomicAdd(&gs[o >> 3], sum);
    atomicAdd(&gq[o >> 3], sq);
    __syncthreads();
    double M = 8.0 * NK;
    double mean = gs[o >> 3] / M;
    double var = gq[o >> 3] / M - mean * mean;
    if (var < 0.0) var = 0.0;
    double rstd = 1.0 / sqrt(var + 1e-6);
    float a = (float)rstd * gw[o];
    float cs = gb[o] - (float)(mean * rstd) * gw[o];
    aOut[b * 128 + o] = a;
    cOut[b * 128 + o] = cs + (float)bo * a;
}

// ---------------- fp16 mma conv: 128n x 64o CTA tile, 64-col K chunks ------
// 8 warps: wr = w&3 -> 32-n quarter, wc = w>>2 -> 32-o half
// SMEM: 3 stages x (X 128x128B + W 64x128B) = 73728, + 256 stats
enum { EPI_LEAKY02 = 0, EPI_STATS = 1, EPI_TRANS_STATS = 2, EPI_FINAL = 3 };
static constexpr int CONV_SMEM = 3 * 24576 + 256;

template <int O, int C, int EPI, int GSIZE>
__global__ __launch_bounds__(256, 3) void mma_conv_f16(
    const __half* __restrict__ Wh, const float* __restrict__ bias,
    const __half* __restrict__ in, void* __restrict__ outv,
    const float* __restrict__ aArr, const float* __restrict__ cArr,
    const __half* __restrict__ scpre, float* gsum, float* gsq)
{
    extern __shared__ __align__(16) char smem[];
    const uint32_t sb = smem_u32(smem);
    float* ssh = (float*)(smem + 73728);
    float* sqh = ssh + 16;
    float* osf = (float*)smem;  // [64][132] reuse after mainloop

    const int tid = threadIdx.x;
    const int w = tid >> 5, lane = tid & 31;
    const int wr = w & 3, wc = w >> 2;
    const int t = lane & 3, g = lane >> 2;
    const int n0 = blockIdx.x * 128;
    const int o0 = blockIdx.y * 64;
    const int b = blockIdx.z;

    const __half* xbase = in + ((size_t)b * Nc + n0) * C;
    const __half* wbase = Wh + (size_t)o0 * C;

    // staging: X 128x64 cols (1024 16B-chunks), W 64x64 cols (512 chunks)
    uint32_t sXOff[4], gxOff[4], sWOff[2], gwOff[2];
#pragma unroll
    for (int i = 0; i < 4; ++i) {
        int id = tid + 256 * i;
        int r = id >> 3, c = id & 7;
        sXOff[i] = swoff(r, c);
        gxOff[i] = (uint32_t)(r * C + c * 8);
    }
#pragma unroll
    for (int i = 0; i < 2; ++i) {
        int id = tid + 256 * i;
        int r = id >> 3, c = id & 7;
        sWOff[i] = 16384u + swoff(r, c);
        gwOff[i] = (uint32_t)(r * C + c * 8);
    }

    // ldmatrix constants
    const int quad = lane >> 3, lr = lane & 7;
    const int raA = (quad & 1) * 8 + lr, caA = quad >> 1;
    const int raB = (quad >> 1) * 8 + lr, caB = quad & 1;
    uint32_t rbA[2], rxA[2], rbB[2], rxB[2];
#pragma unroll
    for (int mi = 0; mi < 2; ++mi) {
        int row = wr * 32 + mi * 16 + raA;
        rbA[mi] = (uint32_t)(row * 128);
        rxA[mi] = (uint32_t)(row & 7);
    }
#pragma unroll
    for (int oi = 0; oi < 2; ++oi) {
        int row = wc * 32 + oi * 16 + raB;
        rbB[oi] = 16384u + (uint32_t)(row * 128);
        rxB[oi] = (uint32_t)(row & 7);
    }

    float d[2][4][4];
#pragma unroll
    for (int mi = 0; mi < 2; ++mi)
#pragma unroll
        for (int ni = 0; ni < 4; ++ni)
#pragma unroll
            for (int e = 0; e < 4; ++e) d[mi][ni][e] = 0.f;

    constexpr int NCH = C / 64;
    auto stage = [&](int j) {
        uint32_t base = sb + (uint32_t)(j % 3) * 24576u;
        int cc = j * 64;
#pragma unroll
        for (int i = 0; i < 4; ++i) cpa16(base + sXOff[i], xbase + gxOff[i] + cc);
#pragma unroll
        for (int i = 0; i < 2; ++i) cpa16(base + sWOff[i], wbase + gwOff[i] + cc);
        CP_COMMIT();
    };
    stage(0);
    if (NCH > 1) stage(1);

    for (int j = 0; j < NCH; ++j) {
        if (j + 1 < NCH) CP_WAIT1(); else CP_WAIT0();
        __syncthreads();
        if (j + 2 < NCH) stage(j + 2);
        const uint32_t base = sb + (uint32_t)(j % 3) * 24576u;
#pragma unroll
        for (int kt = 0; kt < 4; ++kt) {
            uint32_t a[2][4], bb[2][4];
#pragma unroll
            for (int mi = 0; mi < 2; ++mi) {
                uint32_t cA = (uint32_t)(kt * 2 + caA) ^ rxA[mi];
                LDSM4(a[mi], base + rbA[mi] + (cA << 4));
            }
#pragma unroll
            for (int oi = 0; oi < 2; ++oi) {
                uint32_t cB = (uint32_t)(kt * 2 + caB) ^ rxB[oi];
                LDSM4(bb[oi], base + rbB[oi] + (cB << 4));
            }
#pragma unroll
            for (int mi = 0; mi < 2; ++mi)
#pragma unroll
                for (int ni = 0; ni < 4; ++ni) {
                    uint32_t bf[2] = {bb[ni >> 1][(ni & 1) * 2],
                                      bb[ni >> 1][(ni & 1) * 2 + 1]};
                    MMA_F16(d[mi][ni], a[mi], bf);
                }
        }
    }

    // ================= epilogues =================
    if constexpr (EPI == EPI_LEAKY02 || EPI == EPI_STATS) {
        __half* out = (__half*)outv;
        if constexpr (EPI == EPI_STATS) {
            if (tid < 16) { ssh[tid] = 0.f; sqh[tid] = 0.f; }
            __syncthreads();
        }
        float js[4] = {0.f, 0.f, 0.f, 0.f}, jq[4] = {0.f, 0.f, 0.f, 0.f};
#pragma unroll
        for (int mi = 0; mi < 2; ++mi) {
            int p = n0 + wr * 32 + mi * 16 + g;
#pragma unroll
            for (int ni = 0; ni < 4; ++ni) {
                int ch = o0 + wc * 32 + ni * 8 + 2 * t;
                float b0 = bias[ch], b1 = bias[ch + 1];
                float v00 = d[mi][ni][0] + b0, v01 = d[mi][ni][1] + b1;
                float v10 = d[mi][ni][2] + b0, v11 = d[mi][ni][3] + b1;
                if constexpr (EPI == EPI_LEAKY02) {
                    v00 = v00 > 0.f ? v00 : 0.2f * v00;
                    v01 = v01 > 0.f ? v01 : 0.2f * v01;
                    v10 = v10 > 0.f ? v10 : 0.2f * v10;
                    v11 = v11 > 0.f ? v11 : 0.2f * v11;
                } else {
                    js[ni] += v00 + v01 + v10 + v11;
                    jq[ni] += v00 * v00 + v01 * v01 + v10 * v10 + v11 * v11;
                }
                *(__half2*)&out[((size_t)b * Nc + p) * O + ch] =
                    __floats2half2_rn(v00, v01);
                *(__half2*)&out[((size_t)b * Nc + p + 8) * O + ch] =
                    __floats2half2_rn(v10, v11);
            }
        }
        if constexpr (EPI == EPI_STATS) {
#pragma unroll
            for (int ni = 0; ni < 4; ++ni) {
                int gl = (wc * 32 + ni * 8) / GSIZE;
                atomicAdd(&ssh[gl], js[ni]);
                atomicAdd(&sqh[gl], jq[ni]);
            }
            __syncthreads();
            constexpr int NG = 64 / GSIZE;
            if (tid < NG) {
                atomicAdd(&gsum[b * 16 + o0 / GSIZE + tid], ssh[tid]);
                atomicAdd(&gsq[b * 16 + o0 / GSIZE + tid], sqh[tid]);
            }
        }
    } else {
        // transpose epilogue via SMEM: write [b][o][n], o-range 64
        __syncthreads();
        if (tid < 16) { ssh[tid] = 0.f; sqh[tid] = 0.f; }
        __syncthreads();
        float js[4] = {0.f, 0.f, 0.f, 0.f}, jq[4] = {0.f, 0.f, 0.f, 0.f};
#pragma unroll
        for (int mi = 0; mi < 2; ++mi) {
            int nr = wr * 32 + mi * 16 + g;
#pragma unroll
            for (int ni = 0; ni < 4; ++ni) {
                int oc = wc * 32 + ni * 8 + 2 * t;
                float b0 = 0.f, b1 = 0.f;
                if constexpr (EPI == EPI_TRANS_STATS) {
                    b0 = bias[o0 + oc]; b1 = bias[o0 + oc + 1];
                }
                float v00 = d[mi][ni][0] + b0, v01 = d[mi][ni][1] + b1;
                float v10 = d[mi][ni][2] + b0, v11 = d[mi][ni][3] + b1;
                if constexpr (EPI == EPI_TRANS_STATS) {
                    js[ni] += v00 + v01 + v10 + v11;
                    jq[ni] += v00 * v00 + v01 * v01 + v10 * v10 + v11 * v11;
                }
                osf[oc * 132 + nr] = v00;
                osf[(oc + 1) * 132 + nr] = v01;
                osf[oc * 132 + nr + 8] = v10;
                osf[(oc + 1) * 132 + nr + 8] = v11;
            }
        }
        if constexpr (EPI == EPI_TRANS_STATS) {
#pragma unroll
            for (int ni = 0; ni < 4; ++ni) {
                int gl = (wc * 32 + ni * 8) / GSIZE;
                atomicAdd(&ssh[gl], js[ni]);
                atomicAdd(&sqh[gl], jq[ni]);
            }
        }
        __syncthreads();
#pragma unroll
        for (int rr = 0; rr < 8; ++rr) {
            int r = w + rr * 8;
            int og = o0 + r;
            float4 v = *(float4*)&osf[r * 132 + lane * 4];
            if constexpr (EPI == EPI_FINAL) {
                float* op = (float*)outv + ((size_t)b * O + og) * Nc + n0;
                float bi = bias[og];
                float av = aArr[(size_t)b * O + og];
                float cv = cArr[(size_t)b * O + og];
                uint2 sraw = *(const uint2*)(scpre +
                    ((size_t)b * O + og) * Nc + n0 + lane * 4);
                float2 s0 = __half22float2(*(__half2*)&sraw.x);
                float2 s1 = __half22float2(*(__half2*)&sraw.y);
                float ss[4] = {s0.x, s0.y, s1.x, s1.y};
                float4 rrv;
#pragma unroll
                for (int e = 0; e < 4; ++e) {
                    float x = (&v.x)[e] + bi + fmaf(ss[e], av, cv);
                    (&rrv.x)[e] = x > 0.f ? x : 0.01f * x;
                }
                *(float4*)(op + lane * 4) = rrv;
            } else {
                __half* op = (__half*)outv + ((size_t)b * O + og) * Nc + n0;
                uint2 st;
                *(__half2*)&st.x = __floats2half2_rn(v.x, v.y);
                *(__half2*)&st.y = __floats2half2_rn(v.z, v.w);
                *(uint2*)(op + lane * 4) = st;
            }
        }
        if constexpr (EPI == EPI_TRANS_STATS) {
            constexpr int NG = 64 / GSIZE;
            if (tid < NG) {
                atomicAdd(&gsum[b * 16 + o0 / GSIZE + tid], ssh[tid]);
                atomicAdd(&gsq[b * 16 + o0 / GSIZE + tid], sqh[tid]);
            }
        }
    }
}

// ---------------- pool GN finalize ----------------
__global__ void pool_finalize_kernel(const float* __restrict__ sum, const float* __restrict__ sq,
                                     const float* __restrict__ gw, const float* __restrict__ gb,
                                     float* __restrict__ aOut, float* __restrict__ cOut,
                                     int Cc, int gsize, float Minv)
{
    int b = blockIdx.x, o = threadIdx.x;
    int g = o / gsize;
    float mean = sum[b * 16 + g] * Minv;
    float var = sq[b * 16 + g] * Minv - mean * mean;
    var = fmaxf(var, 0.f);
    float rstd = rsqrtf(var + 1e-6f);
    float a = rstd * gw[o];
    aOut[(size_t)b * Cc + o] = a;
    cOut[(size_t)b * Cc + o] = gb[o] - mean * a;
}

// ---------------- normalize p2 -> x3 (half, affine+relu) -------------------
__global__ __launch_bounds__(256) void normalize_h_kernel(
    const __half* __restrict__ p, __half* __restrict__ x,
    const float* __restrict__ aA, const float* __restrict__ cA)
{
    size_t i = ((size_t)blockIdx.x * blockDim.x + threadIdx.x) * 4;
    int c = (int)(i % 256);
    int b = (int)(i / ((size_t)Nc * 256));
    __half2 v0 = *(const __half2*)(p + i);
    __half2 v1 = *(const __half2*)(p + i + 2);
    float4 av = *(const float4*)(aA + (size_t)b * 256 + c);
    float4 cv = *(const float4*)(cA + (size_t)b * 256 + c);
    float r0 = fmaxf(fmaf(__half2float(v0.x), av.x, cv.x), 0.f);
    float r1 = fmaxf(fmaf(__half2float(v0.y), av.y, cv.y), 0.f);
    float r2 = fmaxf(fmaf(__half2float(v1.x), av.z, cv.z), 0.f);
    float r3 = fmaxf(fmaf(__half2float(v1.y), av.w, cv.w), 0.f);
    *(__half2*)(x + i) = __floats2half2_rn(r0, r1);
    *(__half2*)(x + i + 2) = __floats2half2_rn(r2, r3);
}

// ---------------- fused LSE (combined weights + half2 gather) ---------------
static constexpr int PTS = 8;
template <bool AFF>
__global__ __launch_bounds__(128) void lse_apply_kernel(
    const float* __restrict__ coords, const int* __restrict__ knn_idx,
    const float* __restrict__ knn_dist, const float* __restrict__ w,
    const float* __restrict__ aArr, const float* __restrict__ cArr,
    const __half* __restrict__ xsrc, __half* __restrict__ mout,
    const float* __restrict__ aN, const float* __restrict__ cN)
{
    __shared__ int sh_idx[PTS * 16];
    __shared__ float sh_nbr[PTS * 16][3];
    __shared__ float sh_dist[PTS * 16];
    __shared__ float sh_ctr[PTS][3];
    __shared__ float2 spart[PTS][64];

    const int b = blockIdx.y;
    const int n0 = blockIdx.x * PTS;
    const int tid = threadIdx.x;
    const float* cb = coords + (size_t)b * Nc * 3;

    if (tid < PTS * 16) {
        size_t base = ((size_t)b * Nc + n0) * 16 + tid;
        sh_idx[tid] = knn_idx[base];
        sh_dist[tid] = knn_dist[base];
    }
    if (tid < PTS * 3) sh_ctr[tid / 3][tid % 3] = cb[n0 * 3 + tid];
    __syncthreads();
    if (tid < PTS * 16) {
        int j = sh_idx[tid];
        sh_nbr[tid][0] = cb[j * 3 + 0];
        sh_nbr[tid][1] = cb[j * 3 + 1];
        sh_nbr[tid][2] = cb[j * 3 + 2];
    }
    // combined geo weights: dot = wc.c + wn.n + wd*d
    float w0 = w[tid * 10 + 0], w1 = w[tid * 10 + 1], w2 = w[tid * 10 + 2];
    float w3 = w[tid * 10 + 3], w4 = w[tid * 10 + 4], w5 = w[tid * 10 + 5];
    float w6 = w[tid * 10 + 6], w7 = w[tid * 10 + 7], w8 = w[tid * 10 + 8];
    float wd = w[tid * 10 + 9];
    const float wcx = w0 + w6, wcy = w1 + w7, wcz = w2 + w8;
    const float wnx = w3 - w6, wny = w4 - w7, wnz = w5 - w8;
    const float a = aArr[b * 128 + tid];
    const float cc = cArr[b * 128 + tid];

    // gather role: channel pair cp (2 channels), k-half h
    const int cp = tid & 63, h = tid >> 6;
    float an0 = 0.f, an1 = 0.f, cn0 = 0.f, cn1 = 0.f;
    if (AFF) {
        an0 = aN[b * 128 + 2 * cp]; an1 = aN[b * 128 + 2 * cp + 1];
        cn0 = cN[b * 128 + 2 * cp]; cn1 = cN[b * 128 + 2 * cp + 1];
    }
    const __half* xb = xsrc + (size_t)b * Nc * 128;
    __syncthreads();

    float2 accn[PTS];
#pragma unroll
    for (int pi = 0; pi < PTS; pi++) {
        // geo: channel tid
        float cx = sh_ctr[pi][0], cy = sh_ctr[pi][1], cz = sh_ctr[pi][2];
        float dotc = wcx * cx + wcy * cy + wcz * cz;
        float accg = 0.f;
#pragma unroll
        for (int k = 0; k < 16; k++) {
            int s = pi * 16 + k;
            float dot = dotc + wnx * sh_nbr[s][0] + wny * sh_nbr[s][1] +
                        wnz * sh_nbr[s][2] + wd * sh_dist[s];
            accg += fmaxf(fmaf(dot, a, cc), 0.f);
        }
        mout[((size_t)b * Nc + n0 + pi) * 256 + tid] = __float2half(accg * 0.0625f);

        // gather: channels 2cp,2cp+1 over k in [8h, 8h+8)
        float2 acc = make_float2(0.f, 0.f);
#pragma unroll
        for (int k = 0; k < 8; k++) {
            int s = pi * 16 + h * 8 + k;
            int j = sh_idx[s];
            float2 f = __half22float2(*(const __half2*)&xb[(size_t)j * 128 + 2 * cp]);
            if (AFF) {
                f.x = fmaxf(fmaf(f.x, an0, cn0), 0.f);
                f.y = fmaxf(fmaf(f.y, an1, cn1), 0.f);
            }
            acc.x += f.x; acc.y += f.y;
        }
        if (h == 1) spart[pi][cp] = acc;
        accn[pi] = acc;
    }
    __syncthreads();
    if (h == 0) {
#pragma unroll
        for (int pi = 0; pi < PTS; pi++) {
            float2 o = spart[pi][cp];
            o.x = (o.x + accn[pi].x) * 0.0625f;
            o.y = (o.y + accn[pi].y) * 0.0625f;
            *(__half2*)&mout[((size_t)b * Nc + n0 + pi) * 256 + 128 + 2 * cp] =
                __floats2half2_rn(o.x, o.y);
        }
    }
}

// ---------------- host ----------------
#define SYM(ty, p, s) do { void* _t; cudaGetSymbolAddress(&_t, s); p = (ty)_t; } while (0)

extern "C" void kernel_launch(void* const* d_in, const int* in_sizes, int n_in,
                              void* d_out, int out_size)
{
    (void)in_sizes; (void)n_in; (void)out_size;
    const float* coords   = (const float*)d_in[0];
    const float* features = (const float*)d_in[1];
    const float* knn_dist = (const float*)d_in[2];
    const int*   knn_idx  = (const int*)d_in[3];
    const float* w1       = (const float*)d_in[4];
    const float* b1       = (const float*)d_in[5];
    const float* lse1_w   = (const float*)d_in[6];
    const float* lse1_b   = (const float*)d_in[7];
    const float* lse1_gw  = (const float*)d_in[8];
    const float* lse1_gb  = (const float*)d_in[9];
    const float* pool1_w  = (const float*)d_in[10];
    const float* pool1_b  = (const float*)d_in[11];
    const float* pool1_gw = (const float*)d_in[12];
    const float* pool1_gb = (const float*)d_in[13];
    const float* lse2_w   = (const float*)d_in[14];
    const float* lse2_b   = (const float*)d_in[15];
    const float* lse2_gw  = (const float*)d_in[16];
    const float* lse2_gb  = (const float*)d_in[17];
    const float* pool2_w  = (const float*)d_in[18];
    const float* pool2_b  = (const float*)d_in[19];
    const float* pool2_gw = (const float*)d_in[20];
    const float* pool2_gb = (const float*)d_in[21];
    const float* mlp2_w   = (const float*)d_in[22];
    const float* mlp2_b   = (const float*)d_in[23];
    const float* sc_w     = (const float*)d_in[24];
    const float* sc_b     = (const float*)d_in[25];
    const float* sc_gw    = (const float*)d_in[26];
    const float* sc_gb    = (const float*)d_in[27];
    float* out = (float*)d_out;

    __half *fT, *wh, *x1, *m1, *p1, *m2, *p2, *x3, *scp;
    float *l1a, *l1c, *l2a, *l2c;
    float *p1s, *p1q, *p2s, *p2q, *scs, *scq;
    float *pa1, *pc1, *pa2, *pc2, *sca, *scc;
    SYM(__half*, fT, g_fT); SYM(__half*, wh, g_wh);
    SYM(__half*, x1, g_x1); SYM(__half*, m1, g_m1); SYM(__half*, p1, g_p1);
    SYM(__half*, m2, g_m2); SYM(__half*, p2, g_p2); SYM(__half*, x3, g_x3);
    SYM(__half*, scp, g_scp);
    SYM(float*, l1a, g_lse1a); SYM(float*, l1c, g_lse1c);
    SYM(float*, l2a, g_lse2a); SYM(float*, l2c, g_lse2c);
    SYM(float*, p1s, g_p1s); SYM(float*, p1q, g_p1q);
    SYM(float*, p2s, g_p2s); SYM(float*, p2q, g_p2q);
    SYM(float*, scs, g_scs); SYM(float*, scq, g_scq);
    SYM(float*, pa1, g_pa1); SYM(float*, pc1, g_pc1);
    SYM(float*, pa2, g_pa2); SYM(float*, pc2, g_pc2);
    SYM(float*, sca, g_sca); SYM(float*, scc, g_scc);

    cudaFuncSetAttribute(mma_conv_f16<512, 128, EPI_TRANS_STATS, 32>,
                         cudaFuncAttributeMaxDynamicSharedMemorySize, CONV_SMEM);
    cudaFuncSetAttribute(mma_conv_f16<128, 128, EPI_LEAKY02, 8>,
                         cudaFuncAttributeMaxDynamicSharedMemorySize, CONV_SMEM);
    cudaFuncSetAttribute(mma_conv_f16<128, 256, EPI_STATS, 8>,
                         cudaFuncAttributeMaxDynamicSharedMemorySize, CONV_SMEM);
    cudaFuncSetAttribute(mma_conv_f16<256, 256, EPI_STATS, 16>,
                         cudaFuncAttributeMaxDynamicSharedMemorySize, CONV_SMEM);
    cudaFuncSetAttribute(mma_conv_f16<512, 256, EPI_FINAL, 8>,
                         cudaFuncAttributeMaxDynamicSharedMemorySize, CONV_SMEM);

    prep_kernel<<<256, 256>>>(w1, pool1_w, pool2_w, sc_w, mlp2_w);
    transpose_f16_kernel<<<dim3(Nc / 32, 4, Bc), 256>>>(features, fT);
    // shortcut conv (independent): -> scp [b][o][n] fp16, + stats
    mma_conv_f16<512, 128, EPI_TRANS_STATS, 32>
        <<<dim3(Nc / 128, 8, Bc), 256, CONV_SMEM>>>(wh + WOFF_SC, sc_b, fT, scp,
                                                    nullptr, nullptr, nullptr, scs, scq);
    // mlp1
    mma_conv_f16<128, 128, EPI_LEAKY02, 8>
        <<<dim3(Nc / 128, 2, Bc), 256, CONV_SMEM>>>(wh + WOFF_W1, b1, fT, x1,
                                                    nullptr, nullptr, nullptr, nullptr, nullptr);
    geo_moments_kernel<<<dim3(64, Bc), 256>>>(coords, knn_idx, knn_dist);
    lse_finalize_kernel<<<dim3(Bc, 2), 128>>>(lse1_w, lse1_b, lse1_gw, lse1_gb,
                                              lse2_w, lse2_b, lse2_gw, lse2_gb,
                                              l1a, l1c, l2a, l2c);
    lse_apply_kernel<false><<<dim3(Nc / PTS, Bc), 128>>>(
        coords, knn_idx, knn_dist, lse1_w, l1a, l1c, x1, m1, nullptr, nullptr);
    mma_conv_f16<128, 256, EPI_STATS, 8>
        <<<dim3(Nc / 128, 2, Bc), 256, CONV_SMEM>>>(wh + WOFF_P1, pool1_b, m1, p1,
                                                    nullptr, nullptr, nullptr, p1s, p1q);
    pool_finalize_kernel<<<Bc, 128>>>(p1s, p1q, pool1_gw, pool1_gb, pa1, pc1,
                                      128, 8, 1.f / (8.f * Nc));
    lse_apply_kernel<true><<<dim3(Nc / PTS, Bc), 128>>>(
        coords, knn_idx, knn_dist, lse2_w, l2a, l2c, p1, m2, pa1, pc1);
    mma_conv_f16<256, 256, EPI_STATS, 16>
        <<<dim3(Nc / 128, 4, Bc), 256, CONV_SMEM>>>(wh + WOFF_P2, pool2_b, m2, p2,
                                                    nullptr, nullptr, nullptr, p2s, p2q);
    pool_finalize_kernel<<<Bc, 256>>>(p2s, p2q, pool2_gw, pool2_gb, pa2, pc2,
                                      256, 16, 1.f / (16.f * Nc));
    normalize_h_kernel<<<(Bc * Nc * 256) / 1024, 256>>>(p2, x3, pa2, pc2);
    pool_finalize_kernel<<<Bc, 512>>>(scs, scq, sc_gw, sc_gb, sca, scc,
                                      512, 32, 1.f / (32.f * Nc));
    // final: mlp2 conv + shortcut GN + leaky(0.01) -> out [b][o][n] fp32
    mma_conv_f16<512, 256, EPI_FINAL, 8>
        <<<dim3(Nc / 128, 8, Bc), 256, CONV_SMEM>>>(wh + WOFF_M2, mlp2_b, x3, out,
                                                    sca, scc, scp, nullptr, nullptr);
}

// round 9
// speedup vs baseline: 1.2691x; 1.2691x over previous
#include <cuda_runtime.h>
#include <cuda_fp16.h>
#include <stdint.h>
#include <math.h>

static constexpr int Bc = 2;
static constexpr int Nc = 16384;
static constexpr int Kc = 16;

// ---------------- scratch ----------------
__device__ __half g_fT[(size_t)Bc * Nc * 128];   // features transposed [b][n][c]
__device__ __half g_wh[311296];                  // all conv weights as fp16
__device__ __half g_x1[(size_t)Bc * Nc * 128];   // mlp1 out  [b][n][c]
__device__ __half g_m1[(size_t)Bc * Nc * 256];   // lse1 pooled mean
__device__ __half g_p1[(size_t)Bc * Nc * 128];   // pool1 pre-GN
__device__ __half g_m2[(size_t)Bc * Nc * 256];   // lse2 pooled mean
__device__ __half g_p2[(size_t)Bc * Nc * 256];   // pool2 pre-GN
__device__ __half g_x3[(size_t)Bc * Nc * 256];   // pool2 out
__device__ __half g_scp[(size_t)Bc * Nc * 512];  // shortcut pre-GN, [b][o][n] fp16

__device__ double g_geoS[Bc * 10];
__device__ double g_geoG[Bc * 55];
__device__ float g_lse1a[Bc * 128], g_lse1c[Bc * 128];
__device__ float g_lse2a[Bc * 128], g_lse2c[Bc * 128];
__device__ float g_p1s[Bc * 16], g_p1q[Bc * 16];
__device__ float g_p2s[Bc * 16], g_p2q[Bc * 16];
__device__ float g_scs[Bc * 16], g_scq[Bc * 16];
__device__ float g_pa1[Bc * 128], g_pc1[Bc * 128];
__device__ float g_pa2[Bc * 256], g_pc2[Bc * 256];
__device__ float g_sca[Bc * 512], g_scc[Bc * 512];

// weight blob offsets (in halves)
static constexpr int WOFF_W1 = 0;
static constexpr int WOFF_P1 = 16384;
static constexpr int WOFF_P2 = 49152;
static constexpr int WOFF_SC = 114688;
static constexpr int WOFF_M2 = 180224;
static constexpr int WTOT = 311296;

// ---------------- helpers ----------------
__device__ __forceinline__ uint32_t smem_u32(const void* p) {
    uint32_t a;
    asm("{ .reg .u64 t; cvta.to.shared.u64 t, %1; cvt.u32.u64 %0, t; }" : "=r"(a) : "l"(p));
    return a;
}
__device__ __forceinline__ void cpa16(uint32_t dst, const void* src) {
    asm volatile("cp.async.cg.shared.global [%0], [%1], 16;" :: "r"(dst), "l"(src));
}
#define CP_COMMIT() asm volatile("cp.async.commit_group;" ::: "memory")
#define CP_WAIT1() asm volatile("cp.async.wait_group 1;" ::: "memory")
#define CP_WAIT0() asm volatile("cp.async.wait_group 0;" ::: "memory")

#define MMA_F16(d, a, b) \
    asm volatile("mma.sync.aligned.m16n8k16.row.col.f32.f16.f16.f32 " \
        "{%0,%1,%2,%3}, {%4,%5,%6,%7}, {%8,%9}, {%0,%1,%2,%3};" \
        : "+f"((d)[0]), "+f"((d)[1]), "+f"((d)[2]), "+f"((d)[3]) \
        : "r"((a)[0]), "r"((a)[1]), "r"((a)[2]), "r"((a)[3]), \
          "r"((b)[0]), "r"((b)[1]))

#define LDSM4(r, addr) \
    asm volatile("ldmatrix.sync.aligned.m8n8.x4.shared.b16 {%0,%1,%2,%3}, [%4];" \
        : "=r"((r)[0]), "=r"((r)[1]), "=r"((r)[2]), "=r"((r)[3]) : "r"(addr))

// swizzled offset within a row-major 128B-row tile: row r, 16B-chunk c (0..7)
__device__ __forceinline__ uint32_t swoff(int r, int c) {
    return (uint32_t)(r * 128 + ((c ^ (r & 7)) << 4));
}

// ---------------- prep: zero stats + convert weights to fp16 ----------------
__global__ __launch_bounds__(256) void prep_kernel(
    const float* __restrict__ w1, const float* __restrict__ pw1,
    const float* __restrict__ pw2, const float* __restrict__ scw,
    const float* __restrict__ mw)
{
    if (blockIdx.x == 0) {
        int t = threadIdx.x;
        if (t < Bc * 10) g_geoS[t] = 0.0;
        if (t < Bc * 55) g_geoG[t] = 0.0;
        if (t < Bc * 16) {
            g_p1s[t] = 0.f; g_p1q[t] = 0.f;
            g_p2s[t] = 0.f; g_p2q[t] = 0.f;
            g_scs[t] = 0.f; g_scq[t] = 0.f;
        }
    }
    for (int i = blockIdx.x * blockDim.x + threadIdx.x; i < WTOT;
         i += gridDim.x * blockDim.x) {
        float v;
        if (i < WOFF_P1) v = w1[i];
        else if (i < WOFF_P2) v = pw1[i - WOFF_P1];
        else if (i < WOFF_SC) v = pw2[i - WOFF_P2];
        else if (i < WOFF_M2) v = scw[i - WOFF_SC];
        else v = mw[i - WOFF_M2];
        g_wh[i] = __float2half(v);
    }
}

// ---------------- transpose features [b][c][n] fp32 -> [b][n][c] fp16 -------
__global__ __launch_bounds__(256) void transpose_f16_kernel(
    const float* __restrict__ in, __half* __restrict__ outp)
{
    __shared__ float t[32][33];
    int b = blockIdx.z;
    int cB = blockIdx.y * 32, nB = blockIdx.x * 32;
    int tx = threadIdx.x & 31, ty = threadIdx.x >> 5;
#pragma unroll
    for (int i = 0; i < 4; ++i)
        t[ty + 8 * i][tx] = in[((size_t)b * 128 + cB + ty + 8 * i) * Nc + nB + tx];
    __syncthreads();
#pragma unroll
    for (int i = 0; i < 4; ++i)
        outp[((size_t)b * Nc + nB + ty + 8 * i) * 128 + cB + tx] =
            __float2half(t[tx][ty + 8 * i]);
}

// ---------------- geo moments ----------------
__global__ __launch_bounds__(256) void geo_moments_kernel(
    const float* __restrict__ coords, const int* __restrict__ knn_idx,
    const float* __restrict__ knn_dist)
{
    const int b = blockIdx.y;
    const float* cb = coords + (size_t)b * Nc * 3;
    float S[10];
    float G[55];
#pragma unroll
    for (int c = 0; c < 10; c++) S[c] = 0.f;
#pragma unroll
    for (int p = 0; p < 55; p++) G[p] = 0.f;

    for (int it = blockIdx.x * blockDim.x + threadIdx.x; it < Nc * Kc;
         it += gridDim.x * blockDim.x) {
        int n = it >> 4;
        size_t base = ((size_t)b * Nc + n) * Kc + (it & 15);
        float cx = cb[n * 3 + 0], cy = cb[n * 3 + 1], cz = cb[n * 3 + 2];
        int j = knn_idx[base];
        float nx = cb[j * 3 + 0], ny = cb[j * 3 + 1], nz = cb[j * 3 + 2];
        float dd = knn_dist[base];
        float g[10] = {cx, cy, cz, nx, ny, nz, cx - nx, cy - ny, cz - nz, dd};
        int p = 0;
#pragma unroll
        for (int c = 0; c < 10; c++) {
            S[c] += g[c];
#pragma unroll
            for (int d = c; d < 10; d++) G[p++] += g[c] * g[d];
        }
    }
#pragma unroll
    for (int c = 0; c < 10; c++)
        for (int off = 16; off; off >>= 1) S[c] += __shfl_xor_sync(~0u, S[c], off);
#pragma unroll
    for (int p = 0; p < 55; p++)
        for (int off = 16; off; off >>= 1) G[p] += __shfl_xor_sync(~0u, G[p], off);
    if ((threadIdx.x & 31) == 0) {
        for (int c = 0; c < 10; c++) atomicAdd(&g_geoS[b * 10 + c], (double)S[c]);
        for (int p = 0; p < 55; p++) atomicAdd(&g_geoG[b * 55 + p], (double)G[p]);
    }
}

// ---------------- closed-form GN stats for BOTH LSE layers -----------------
__global__ void lse_finalize_kernel(
    const float* __restrict__ w1p, const float* __restrict__ b1p,
    const float* __restrict__ gw1, const float* __restrict__ gb1,
    const float* __restrict__ w2p, const float* __restrict__ b2p,
    const float* __restrict__ gw2, const float* __restrict__ gb2,
    float* __restrict__ a1o, float* __restrict__ c1o,
    float* __restrict__ a2o, float* __restrict__ c2o)
{
    int b = blockIdx.x;
    int layer = blockIdx.y;
    const float* w = layer ? w2p : w1p;
    const float* bias = layer ? b2p : b1p;
    const float* gw = layer ? gw2 : gw1;
    const float* gb = layer ? gb2 : gb1;
    float* aOut = layer ? a2o : a1o;
    float* cOut = layer ? c2o : c1o;

    int o = threadIdx.x;  // 128
    float wr[10];
#pragma unroll
    for (int c = 0; c < 10; c++) wr[c] = w[o * 10 + c];
    double t1 = 0.0;
#pragma unroll
    for (int c = 0; c < 10; c++) t1 += (double)wr[c] * g_geoS[b * 10 + c];
    double t2 = 0.0;
    int p = 0;
#pragma unroll
    for (int c = 0; c < 10; c++)
#pragma unroll
        for (int d = c; d < 10; d++) {
            double gv = g_geoG[b * 55 + p]; p++;
            double ww = (double)wr[c] * (double)wr[d];
            t2 += (c == d ? ww : 2.0 * ww) * gv;
        }
    double NK = (double)Nc * (double)Kc;
    double bo = (double)bias[o];
    double sum = t1 + bo * NK;
    double sq  = t2 + 2.0 * bo * t1 + bo * bo * NK;

    __shared__ double gs[16], gq[16];
    if (o < 16) { gs[o] = 0.0; gq[o] = 0.0; }
    __syncthreads();
    atomicAdd(&gs[o >> 3], sum);
    atomicAdd(&gq[o >> 3], sq);
    __syncthreads();
    double M = 8.0 * NK;
    double mean = gs[o >> 3] / M;
    double var = gq[o >> 3] / M - mean * mean;
    if (var < 0.0) var = 0.0;
    double rstd = 1.0 / sqrt(var + 1e-6);
    float a = (float)rstd * gw[o];
    float cs = gb[o] - (float)(mean * rstd) * gw[o];
    aOut[b * 128 + o] = a;
    cOut[b * 128 + o] = cs + (float)bo * a;
}

// ---------------- fp16 mma conv: 128n x 128o CTA tile, 64-col K chunks -----
// warp layout: wr = w&1 -> 64-n half, wc = w>>1 -> 32-o quarter
// SMEM: 3 stages x (X 128x128B + W 128x128B) = 98304, + 256 stats
enum { EPI_LEAKY02 = 0, EPI_STATS = 1, EPI_TRANS_STATS = 2, EPI_FINAL = 3 };
static constexpr int CONV_SMEM = 3 * 32768 + 256;
static constexpr int OSH_STRIDE = 136;  // halves; 272B rows, 16B-aligned

template <int O, int C, int EPI, int GSIZE>
__global__ __launch_bounds__(256, 2) void mma_conv_f16(
    const __half* __restrict__ Wh, const float* __restrict__ bias,
    const __half* __restrict__ in, void* __restrict__ outv,
    const float* __restrict__ aArr, const float* __restrict__ cArr,
    const __half* __restrict__ scpre, float* gsum, float* gsq)
{
    extern __shared__ __align__(16) char smem[];
    const uint32_t sb = smem_u32(smem);
    float* ssh = (float*)(smem + 98304);
    float* sqh = ssh + 16;
    float* osf = (float*)smem;            // [64][132] fp32, TRANS/FINAL epilogue
    __half* osh = (__half*)smem;          // [128][OSH_STRIDE] fp16, LEAKY/STATS

    const int tid = threadIdx.x;
    const int w = tid >> 5, lane = tid & 31;
    const int wr = w & 1, wc = w >> 1;
    const int t = lane & 3, g = lane >> 2;
    const int n0 = blockIdx.x * 128;
    const int o0 = blockIdx.y * 128;
    const int b = blockIdx.z;

    const __half* xbase = in + ((size_t)b * Nc + n0) * C;
    const __half* wbase = Wh + (size_t)o0 * C;

    // staging roles: 128x8 chunks, 256 threads -> 4 chunks each for X and W
    uint32_t sOff[4];
    const __half* gxp[4];
    const __half* gwp[4];
#pragma unroll
    for (int i = 0; i < 4; ++i) {
        int id = tid + 256 * i;
        int r = id >> 3, c = id & 7;
        sOff[i] = swoff(r, c);
        gxp[i] = xbase + (size_t)r * C + c * 8;
        gwp[i] = wbase + (size_t)r * C + c * 8;
    }

    // ldmatrix row constants
    const int quad = lane >> 3, lr = lane & 7;
    const int raA = (quad & 1) * 8 + lr, caA = quad >> 1;
    const int raB = (quad >> 1) * 8 + lr, caB = quad & 1;
    uint32_t rbA[4], rxA[4];
#pragma unroll
    for (int mi = 0; mi < 4; ++mi) {
        int row = wr * 64 + mi * 16 + raA;
        rbA[mi] = (uint32_t)(row * 128);
        rxA[mi] = (uint32_t)(row & 7);
    }
    uint32_t rbB[2], rxB[2];
#pragma unroll
    for (int oi = 0; oi < 2; ++oi) {
        int row = wc * 32 + oi * 16 + raB;
        rbB[oi] = 16384u + (uint32_t)(row * 128);
        rxB[oi] = (uint32_t)(row & 7);
    }

    float d[4][4][4];
#pragma unroll
    for (int mi = 0; mi < 4; ++mi)
#pragma unroll
        for (int ni = 0; ni < 4; ++ni)
#pragma unroll
            for (int e = 0; e < 4; ++e) d[mi][ni][e] = 0.f;

    constexpr int NCH = C / 64;
    auto stage = [&](int j) {
        uint32_t base = sb + (uint32_t)(j % 3) * 32768u;
        int cc = j * 64;
#pragma unroll
        for (int i = 0; i < 4; ++i) {
            cpa16(base + sOff[i], gxp[i] + cc);
            cpa16(base + 16384 + sOff[i], gwp[i] + cc);
        }
        CP_COMMIT();
    };
    stage(0);
    if (NCH > 1) stage(1);

    for (int j = 0; j < NCH; ++j) {
        if (j + 1 < NCH) CP_WAIT1(); else CP_WAIT0();
        __syncthreads();
        if (j + 2 < NCH) stage(j + 2);
        const uint32_t base = sb + (uint32_t)(j % 3) * 32768u;
#pragma unroll
        for (int kt = 0; kt < 4; ++kt) {
            uint32_t a[4][4], bb[2][4];
#pragma unroll
            for (int mi = 0; mi < 4; ++mi) {
                uint32_t cA = (uint32_t)(kt * 2 + caA) ^ rxA[mi];
                LDSM4(a[mi], base + rbA[mi] + (cA << 4));
            }
#pragma unroll
            for (int oi = 0; oi < 2; ++oi) {
                uint32_t cB = (uint32_t)(kt * 2 + caB) ^ rxB[oi];
                LDSM4(bb[oi], base + rbB[oi] + (cB << 4));
            }
#pragma unroll
            for (int mi = 0; mi < 4; ++mi)
#pragma unroll
                for (int ni = 0; ni < 4; ++ni) {
                    uint32_t bf[2] = {bb[ni >> 1][(ni & 1) * 2],
                                      bb[ni >> 1][(ni & 1) * 2 + 1]};
                    MMA_F16(d[mi][ni], a[mi], bf);
                }
        }
    }

    // ================= epilogues =================
    if constexpr (EPI == EPI_LEAKY02 || EPI == EPI_STATS) {
        // stage through SMEM fp16 tile [128 n][128 o], then coalesced writes
        __half* out = (__half*)outv;
        __syncthreads();  // mainloop smem reads done; reuse buffers
        if constexpr (EPI == EPI_STATS) {
            if (tid < 16) { ssh[tid] = 0.f; sqh[tid] = 0.f; }
            __syncthreads();
        }
        float js[4] = {0.f, 0.f, 0.f, 0.f}, jq[4] = {0.f, 0.f, 0.f, 0.f};
#pragma unroll
        for (int mi = 0; mi < 4; ++mi) {
            int p = wr * 64 + mi * 16 + g;
#pragma unroll
            for (int ni = 0; ni < 4; ++ni) {
                int ch = wc * 32 + ni * 8 + 2 * t;
                float b0 = bias[o0 + ch], b1 = bias[o0 + ch + 1];
                float v00 = d[mi][ni][0] + b0, v01 = d[mi][ni][1] + b1;
                float v10 = d[mi][ni][2] + b0, v11 = d[mi][ni][3] + b1;
                if constexpr (EPI == EPI_LEAKY02) {
                    v00 = v00 > 0.f ? v00 : 0.2f * v00;
                    v01 = v01 > 0.f ? v01 : 0.2f * v01;
                    v10 = v10 > 0.f ? v10 : 0.2f * v10;
                    v11 = v11 > 0.f ? v11 : 0.2f * v11;
                } else {
                    js[ni] += v00 + v01 + v10 + v11;
                    jq[ni] += v00 * v00 + v01 * v01 + v10 * v10 + v11 * v11;
                }
                *(__half2*)&osh[p * OSH_STRIDE + ch] = __floats2half2_rn(v00, v01);
                *(__half2*)&osh[(p + 8) * OSH_STRIDE + ch] = __floats2half2_rn(v10, v11);
            }
        }
        if constexpr (EPI == EPI_STATS) {
#pragma unroll
            for (int ni = 0; ni < 4; ++ni) {
                int gl = (wc * 32 + ni * 8) / GSIZE;
                atomicAdd(&ssh[gl], js[ni]);
                atomicAdd(&sqh[gl], jq[ni]);
            }
        }
        __syncthreads();
        // coalesced writes: 128 rows x 16 uint4 chunks = 2048 chunks
#pragma unroll
        for (int i = 0; i < 8; ++i) {
            int id = tid + 256 * i;
            int row = id >> 4, c16 = id & 15;
            uint4 v = *(uint4*)&osh[row * OSH_STRIDE + c16 * 8];
            *(uint4*)&out[((size_t)b * Nc + n0 + row) * O + o0 + c16 * 8] = v;
        }
        if constexpr (EPI == EPI_STATS) {
            constexpr int NG = 128 / GSIZE;
            if (tid < NG) {
                atomicAdd(&gsum[b * 16 + o0 / GSIZE + tid], ssh[tid]);
                atomicAdd(&gsq[b * 16 + o0 / GSIZE + tid], sqh[tid]);
            }
        }
    } else {
        // transpose epilogues via SMEM (two o-halves): write [b][o][n]
        __syncthreads();
        if (tid < 16) { ssh[tid] = 0.f; sqh[tid] = 0.f; }
        __syncthreads();
#pragma unroll
        for (int p = 0; p < 2; ++p) {
            if ((wc >> 1) == p) {
                float js[4] = {0.f, 0.f, 0.f, 0.f}, jq[4] = {0.f, 0.f, 0.f, 0.f};
#pragma unroll
                for (int mi = 0; mi < 4; ++mi) {
                    int nr = wr * 64 + mi * 16 + g;
#pragma unroll
                    for (int ni = 0; ni < 4; ++ni) {
                        int oc = (wc & 1) * 32 + ni * 8 + 2 * t;
                        float b0 = 0.f, b1 = 0.f;
                        if constexpr (EPI == EPI_TRANS_STATS) {
                            b0 = bias[o0 + p * 64 + oc];
                            b1 = bias[o0 + p * 64 + oc + 1];
                        }
                        float v00 = d[mi][ni][0] + b0, v01 = d[mi][ni][1] + b1;
                        float v10 = d[mi][ni][2] + b0, v11 = d[mi][ni][3] + b1;
                        if constexpr (EPI == EPI_TRANS_STATS) {
                            js[ni] += v00 + v01 + v10 + v11;
                            jq[ni] += v00 * v00 + v01 * v01 + v10 * v10 + v11 * v11;
                        }
                        osf[oc * 132 + nr] = v00;
                        osf[(oc + 1) * 132 + nr] = v01;
                        osf[oc * 132 + nr + 8] = v10;
                        osf[(oc + 1) * 132 + nr + 8] = v11;
                    }
                }
                if constexpr (EPI == EPI_TRANS_STATS) {
#pragma unroll
                    for (int ni = 0; ni < 4; ++ni) {
                        int gl = (p * 64 + (wc & 1) * 32 + ni * 8) / GSIZE;
                        atomicAdd(&ssh[gl], js[ni]);
                        atomicAdd(&sqh[gl], jq[ni]);
                    }
                }
            }
            __syncthreads();
#pragma unroll
            for (int rr = 0; rr < 8; ++rr) {
                int r = w + rr * 8;
                int og = o0 + p * 64 + r;
                float4 v = *(float4*)&osf[r * 132 + lane * 4];
                if constexpr (EPI == EPI_FINAL) {
                    float* op = (float*)outv + ((size_t)b * O + og) * Nc + n0;
                    float bi = bias[og];
                    float av = aArr[(size_t)b * O + og];
                    float cv = cArr[(size_t)b * O + og];
                    uint2 sraw = *(const uint2*)(scpre +
                        ((size_t)b * O + og) * Nc + n0 + lane * 4);
                    float2 s0 = __half22float2(*(__half2*)&sraw.x);
                    float2 s1 = __half22float2(*(__half2*)&sraw.y);
                    float ss[4] = {s0.x, s0.y, s1.x, s1.y};
                    float4 rrv;
#pragma unroll
                    for (int e = 0; e < 4; ++e) {
                        float x = (&v.x)[e] + bi + fmaf(ss[e], av, cv);
                        (&rrv.x)[e] = x > 0.f ? x : 0.01f * x;
                    }
                    *(float4*)(op + lane * 4) = rrv;
                } else {
                    __half* op = (__half*)outv + ((size_t)b * O + og) * Nc + n0;
                    uint2 st;
                    *(__half2*)&st.x = __floats2half2_rn(v.x, v.y);
                    *(__half2*)&st.y = __floats2half2_rn(v.z, v.w);
                    *(uint2*)(op + lane * 4) = st;
                }
            }
            __syncthreads();
        }
        if constexpr (EPI == EPI_TRANS_STATS) {
            constexpr int NG = 128 / GSIZE;
            if (tid < NG) {
                atomicAdd(&gsum[b * 16 + o0 / GSIZE + tid], ssh[tid]);
                atomicAdd(&gsq[b * 16 + o0 / GSIZE + tid], sqh[tid]);
            }
        }
    }
}

// ---------------- pool GN finalize ----------------
__global__ void pool_finalize_kernel(const float* __restrict__ sum, const float* __restrict__ sq,
                                     const float* __restrict__ gw, const float* __restrict__ gb,
                                     float* __restrict__ aOut, float* __restrict__ cOut,
                                     int Cc, int gsize, float Minv)
{
    int b = blockIdx.x, o = threadIdx.x;
    int g = o / gsize;
    float mean = sum[b * 16 + g] * Minv;
    float var = sq[b * 16 + g] * Minv - mean * mean;
    var = fmaxf(var, 0.f);
    float rstd = rsqrtf(var + 1e-6f);
    float a = rstd * gw[o];
    aOut[(size_t)b * Cc + o] = a;
    cOut[(size_t)b * Cc + o] = gb[o] - mean * a;
}

// ---------------- normalize p2 -> x3 (half, affine+relu) -------------------
__global__ __launch_bounds__(256) void normalize_h_kernel(
    const __half* __restrict__ p, __half* __restrict__ x,
    const float* __restrict__ aA, const float* __restrict__ cA)
{
    size_t i = ((size_t)blockIdx.x * blockDim.x + threadIdx.x) * 4;
    int c = (int)(i % 256);
    int b = (int)(i / ((size_t)Nc * 256));
    __half2 v0 = *(const __half2*)(p + i);
    __half2 v1 = *(const __half2*)(p + i + 2);
    float4 av = *(const float4*)(aA + (size_t)b * 256 + c);
    float4 cv = *(const float4*)(cA + (size_t)b * 256 + c);
    float r0 = fmaxf(fmaf(__half2float(v0.x), av.x, cv.x), 0.f);
    float r1 = fmaxf(fmaf(__half2float(v0.y), av.y, cv.y), 0.f);
    float r2 = fmaxf(fmaf(__half2float(v1.x), av.z, cv.z), 0.f);
    float r3 = fmaxf(fmaf(__half2float(v1.y), av.w, cv.w), 0.f);
    *(__half2*)(x + i) = __floats2half2_rn(r0, r1);
    *(__half2*)(x + i + 2) = __floats2half2_rn(r2, r3);
}

// ---------------- fused LSE (combined weights + half2 gather) ---------------
static constexpr int PTS = 8;
template <bool AFF>
__global__ __launch_bounds__(128) void lse_apply_kernel(
    const float* __restrict__ coords, const int* __restrict__ knn_idx,
    const float* __restrict__ knn_dist, const float* __restrict__ w,
    const float* __restrict__ aArr, const float* __restrict__ cArr,
    const __half* __restrict__ xsrc, __half* __restrict__ mout,
    const float* __restrict__ aN, const float* __restrict__ cN)
{
    __shared__ int sh_idx[PTS * 16];
    __shared__ float sh_nbr[PTS * 16][3];
    __shared__ float sh_dist[PTS * 16];
    __shared__ float sh_ctr[PTS][3];
    __shared__ float2 spart[PTS][64];

    const int b = blockIdx.y;
    const int n0 = blockIdx.x * PTS;
    const int tid = threadIdx.x;
    const float* cb = coords + (size_t)b * Nc * 3;

    if (tid < PTS * 16) {
        size_t base = ((size_t)b * Nc + n0) * 16 + tid;
        sh_idx[tid] = knn_idx[base];
        sh_dist[tid] = knn_dist[base];
    }
    if (tid < PTS * 3) sh_ctr[tid / 3][tid % 3] = cb[n0 * 3 + tid];
    __syncthreads();
    if (tid < PTS * 16) {
        int j = sh_idx[tid];
        sh_nbr[tid][0] = cb[j * 3 + 0];
        sh_nbr[tid][1] = cb[j * 3 + 1];
        sh_nbr[tid][2] = cb[j * 3 + 2];
    }
    // combined geo weights: dot = wc.c + wn.n + wd*d
    float w0 = w[tid * 10 + 0], w1 = w[tid * 10 + 1], w2 = w[tid * 10 + 2];
    float w3 = w[tid * 10 + 3], w4 = w[tid * 10 + 4], w5 = w[tid * 10 + 5];
    float w6 = w[tid * 10 + 6], w7 = w[tid * 10 + 7], w8 = w[tid * 10 + 8];
    float wd = w[tid * 10 + 9];
    const float wcx = w0 + w6, wcy = w1 + w7, wcz = w2 + w8;
    const float wnx = w3 - w6, wny = w4 - w7, wnz = w5 - w8;
    const float a = aArr[b * 128 + tid];
    const float cc = cArr[b * 128 + tid];

    // gather role: channel pair cp (2 channels), k-half h
    const int cp = tid & 63, h = tid >> 6;
    float an0 = 0.f, an1 = 0.f, cn0 = 0.f, cn1 = 0.f;
    if (AFF) {
        an0 = aN[b * 128 + 2 * cp]; an1 = aN[b * 128 + 2 * cp + 1];
        cn0 = cN[b * 128 + 2 * cp]; cn1 = cN[b * 128 + 2 * cp + 1];
    }
    const __half* xb = xsrc + (size_t)b * Nc * 128;
    __syncthreads();

    float2 accn[PTS];
#pragma unroll
    for (int pi = 0; pi < PTS; pi++) {
        // geo: channel tid
        float cx = sh_ctr[pi][0], cy = sh_ctr[pi][1], cz = sh_ctr[pi][2];
        float dotc = wcx * cx + wcy * cy + wcz * cz;
        float accg = 0.f;
#pragma unroll
        for (int k = 0; k < 16; k++) {
            int s = pi * 16 + k;
            float dot = dotc + wnx * sh_nbr[s][0] + wny * sh_nbr[s][1] +
                        wnz * sh_nbr[s][2] + wd * sh_dist[s];
            accg += fmaxf(fmaf(dot, a, cc), 0.f);
        }
        mout[((size_t)b * Nc + n0 + pi) * 256 + tid] = __float2half(accg * 0.0625f);

        // gather: channels 2cp,2cp+1 over k in [8h, 8h+8)
        float2 acc = make_float2(0.f, 0.f);
#pragma unroll
        for (int k = 0; k < 8; k++) {
            int s = pi * 16 + h * 8 + k;
            int j = sh_idx[s];
            float2 f = __half22float2(*(const __half2*)&xb[(size_t)j * 128 + 2 * cp]);
            if (AFF) {
                f.x = fmaxf(fmaf(f.x, an0, cn0), 0.f);
                f.y = fmaxf(fmaf(f.y, an1, cn1), 0.f);
            }
            acc.x += f.x; acc.y += f.y;
        }
        if (h == 1) spart[pi][cp] = acc;
        accn[pi] = acc;
    }
    __syncthreads();
    if (h == 0) {
#pragma unroll
        for (int pi = 0; pi < PTS; pi++) {
            float2 o = spart[pi][cp];
            o.x = (o.x + accn[pi].x) * 0.0625f;
            o.y = (o.y + accn[pi].y) * 0.0625f;
            *(__half2*)&mout[((size_t)b * Nc + n0 + pi) * 256 + 128 + 2 * cp] =
                __floats2half2_rn(o.x, o.y);
        }
    }
}

// ---------------- host ----------------
#define SYM(ty, p, s) do { void* _t; cudaGetSymbolAddress(&_t, s); p = (ty)_t; } while (0)

extern "C" void kernel_launch(void* const* d_in, const int* in_sizes, int n_in,
                              void* d_out, int out_size)
{
    (void)in_sizes; (void)n_in; (void)out_size;
    const float* coords   = (const float*)d_in[0];
    const float* features = (const float*)d_in[1];
    const float* knn_dist = (const float*)d_in[2];
    const int*   knn_idx  = (const int*)d_in[3];
    const float* w1       = (const float*)d_in[4];
    const float* b1       = (const float*)d_in[5];
    const float* lse1_w   = (const float*)d_in[6];
    const float* lse1_b   = (const float*)d_in[7];
    const float* lse1_gw  = (const float*)d_in[8];
    const float* lse1_gb  = (const float*)d_in[9];
    const float* pool1_w  = (const float*)d_in[10];
    const float* pool1_b  = (const float*)d_in[11];
    const float* pool1_gw = (const float*)d_in[12];
    const float* pool1_gb = (const float*)d_in[13];
    const float* lse2_w   = (const float*)d_in[14];
    const float* lse2_b   = (const float*)d_in[15];
    const float* lse2_gw  = (const float*)d_in[16];
    const float* lse2_gb  = (const float*)d_in[17];
    const float* pool2_w  = (const float*)d_in[18];
    const float* pool2_b  = (const float*)d_in[19];
    const float* pool2_gw = (const float*)d_in[20];
    const float* pool2_gb = (const float*)d_in[21];
    const float* mlp2_w   = (const float*)d_in[22];
    const float* mlp2_b   = (const float*)d_in[23];
    const float* sc_w     = (const float*)d_in[24];
    const float* sc_b     = (const float*)d_in[25];
    const float* sc_gw    = (const float*)d_in[26];
    const float* sc_gb    = (const float*)d_in[27];
    float* out = (float*)d_out;

    __half *fT, *wh, *x1, *m1, *p1, *m2, *p2, *x3, *scp;
    float *l1a, *l1c, *l2a, *l2c;
    float *p1s, *p1q, *p2s, *p2q, *scs, *scq;
    float *pa1, *pc1, *pa2, *pc2, *sca, *scc;
    SYM(__half*, fT, g_fT); SYM(__half*, wh, g_wh);
    SYM(__half*, x1, g_x1); SYM(__half*, m1, g_m1); SYM(__half*, p1, g_p1);
    SYM(__half*, m2, g_m2); SYM(__half*, p2, g_p2); SYM(__half*, x3, g_x3);
    SYM(__half*, scp, g_scp);
    SYM(float*, l1a, g_lse1a); SYM(float*, l1c, g_lse1c);
    SYM(float*, l2a, g_lse2a); SYM(float*, l2c, g_lse2c);
    SYM(float*, p1s, g_p1s); SYM(float*, p1q, g_p1q);
    SYM(float*, p2s, g_p2s); SYM(float*, p2q, g_p2q);
    SYM(float*, scs, g_scs); SYM(float*, scq, g_scq);
    SYM(float*, pa1, g_pa1); SYM(float*, pc1, g_pc1);
    SYM(float*, pa2, g_pa2); SYM(float*, pc2, g_pc2);
    SYM(float*, sca, g_sca); SYM(float*, scc, g_scc);

    cudaFuncSetAttribute(mma_conv_f16<512, 128, EPI_TRANS_STATS, 32>,
                         cudaFuncAttributeMaxDynamicSharedMemorySize, CONV_SMEM);
    cudaFuncSetAttribute(mma_conv_f16<128, 128, EPI_LEAKY02, 8>,
                         cudaFuncAttributeMaxDynamicSharedMemorySize, CONV_SMEM);
    cudaFuncSetAttribute(mma_conv_f16<128, 256, EPI_STATS, 8>,
                         cudaFuncAttributeMaxDynamicSharedMemorySize, CONV_SMEM);
    cudaFuncSetAttribute(mma_conv_f16<256, 256, EPI_STATS, 16>,
                         cudaFuncAttributeMaxDynamicSharedMemorySize, CONV_SMEM);
    cudaFuncSetAttribute(mma_conv_f16<512, 256, EPI_FINAL, 8>,
                         cudaFuncAttributeMaxDynamicSharedMemorySize, CONV_SMEM);

    prep_kernel<<<256, 256>>>(w1, pool1_w, pool2_w, sc_w, mlp2_w);
    transpose_f16_kernel<<<dim3(Nc / 32, 4, Bc), 256>>>(features, fT);
    // shortcut conv (independent): -> scp [b][o][n] fp16, + stats
    mma_conv_f16<512, 128, EPI_TRANS_STATS, 32>
        <<<dim3(Nc / 128, 4, Bc), 256, CONV_SMEM>>>(wh + WOFF_SC, sc_b, fT, scp,
                                                    nullptr, nullptr, nullptr, scs, scq);
    // mlp1
    mma_conv_f16<128, 128, EPI_LEAKY02, 8>
        <<<dim3(Nc / 128, 1, Bc), 256, CONV_SMEM>>>(wh + WOFF_W1, b1, fT, x1,
                                                    nullptr, nullptr, nullptr, nullptr, nullptr);
    geo_moments_kernel<<<dim3(64, Bc), 256>>>(coords, knn_idx, knn_dist);
    lse_finalize_kernel<<<dim3(Bc, 2), 128>>>(lse1_w, lse1_b, lse1_gw, lse1_gb,
                                              lse2_w, lse2_b, lse2_gw, lse2_gb,
                                              l1a, l1c, l2a, l2c);
    lse_apply_kernel<false><<<dim3(Nc / PTS, Bc), 128>>>(
        coords, knn_idx, knn_dist, lse1_w, l1a, l1c, x1, m1, nullptr, nullptr);
    mma_conv_f16<128, 256, EPI_STATS, 8>
        <<<dim3(Nc / 128, 1, Bc), 256, CONV_SMEM>>>(wh + WOFF_P1, pool1_b, m1, p1,
                                                    nullptr, nullptr, nullptr, p1s, p1q);
    pool_finalize_kernel<<<Bc, 128>>>(p1s, p1q, pool1_gw, pool1_gb, pa1, pc1,
                                      128, 8, 1.f / (8.f * Nc));
    lse_apply_kernel<true><<<dim3(Nc / PTS, Bc), 128>>>(
        coords, knn_idx, knn_dist, lse2_w, l2a, l2c, p1, m2, pa1, pc1);
    mma_conv_f16<256, 256, EPI_STATS, 16>
        <<<dim3(Nc / 128, 2, Bc), 256, CONV_SMEM>>>(wh + WOFF_P2, pool2_b, m2, p2,
                                                    nullptr, nullptr, nullptr, p2s, p2q);
    pool_finalize_kernel<<<Bc, 256>>>(p2s, p2q, pool2_gw, pool2_gb, pa2, pc2,
                                      256, 16, 1.f / (16.f * Nc));
    normalize_h_kernel<<<(Bc * Nc * 256) / 1024, 256>>>(p2, x3, pa2, pc2);
    pool_finalize_kernel<<<Bc, 512>>>(scs, scq, sc_gw, sc_gb, sca, scc,
                                      512, 32, 1.f / (32.f * Nc));
    // final: mlp2 conv + shortcut GN + leaky(0.01) -> out [b][o][n] fp32
    mma_conv_f16<512, 256, EPI_FINAL, 8>
        <<<dim3(Nc / 128, 4, Bc), 256, CONV_SMEM>>>(wh + WOFF_M2, mlp2_b, x3, out,
                                                    sca, scc, scp, nullptr, nullptr);
}

// round 10
// speedup vs baseline: 1.2995x; 1.0240x over previous
#include <cuda_runtime.h>
#include <cuda_fp16.h>
#include <stdint.h>
#include <math.h>

static constexpr int Bc = 2;
static constexpr int Nc = 16384;
static constexpr int Kc = 16;

// ---------------- scratch ----------------
__device__ __half g_fT[(size_t)Bc * Nc * 128];   // features transposed [b][n][c]
__device__ __half g_wh[311296];                  // all conv weights as fp16
__device__ __half g_x1[(size_t)Bc * Nc * 128];   // mlp1 out  [b][n][c]
__device__ __half g_m1[(size_t)Bc * Nc * 256];   // lse1 pooled mean
__device__ __half g_p1[(size_t)Bc * Nc * 128];   // pool1 pre-GN
__device__ __half g_m2[(size_t)Bc * Nc * 256];   // lse2 pooled mean
__device__ __half g_p2[(size_t)Bc * Nc * 256];   // pool2 pre-GN
__device__ __half g_x3[(size_t)Bc * Nc * 256];   // pool2 out
__device__ __half g_scp[(size_t)Bc * Nc * 512];  // shortcut pre-GN, [b][o][n] fp16

__device__ double g_geoS[Bc * 10];
__device__ double g_geoG[Bc * 55];
__device__ float g_lse1a[Bc * 128], g_lse1c[Bc * 128];
__device__ float g_lse2a[Bc * 128], g_lse2c[Bc * 128];
__device__ float g_p1s[Bc * 16], g_p1q[Bc * 16];
__device__ float g_p2s[Bc * 16], g_p2q[Bc * 16];
__device__ float g_scs[Bc * 16], g_scq[Bc * 16];

// weight blob offsets (in halves)
static constexpr int WOFF_W1 = 0;
static constexpr int WOFF_P1 = 16384;
static constexpr int WOFF_P2 = 49152;
static constexpr int WOFF_SC = 114688;
static constexpr int WOFF_M2 = 180224;
static constexpr int WTOT = 311296;

// ---------------- helpers ----------------
__device__ __forceinline__ uint32_t smem_u32(const void* p) {
    uint32_t a;
    asm("{ .reg .u64 t; cvta.to.shared.u64 t, %1; cvt.u32.u64 %0, t; }" : "=r"(a) : "l"(p));
    return a;
}
__device__ __forceinline__ void cpa16(uint32_t dst, const void* src) {
    asm volatile("cp.async.cg.shared.global [%0], [%1], 16;" :: "r"(dst), "l"(src));
}
#define CP_COMMIT() asm volatile("cp.async.commit_group;" ::: "memory")
#define CP_WAIT1() asm volatile("cp.async.wait_group 1;" ::: "memory")
#define CP_WAIT0() asm volatile("cp.async.wait_group 0;" ::: "memory")

#define MMA_F16(d, a, b) \
    asm volatile("mma.sync.aligned.m16n8k16.row.col.f32.f16.f16.f32 " \
        "{%0,%1,%2,%3}, {%4,%5,%6,%7}, {%8,%9}, {%0,%1,%2,%3};" \
        : "+f"((d)[0]), "+f"((d)[1]), "+f"((d)[2]), "+f"((d)[3]) \
        : "r"((a)[0]), "r"((a)[1]), "r"((a)[2]), "r"((a)[3]), \
          "r"((b)[0]), "r"((b)[1]))

#define LDSM4(r, addr) \
    asm volatile("ldmatrix.sync.aligned.m8n8.x4.shared.b16 {%0,%1,%2,%3}, [%4];" \
        : "=r"((r)[0]), "=r"((r)[1]), "=r"((r)[2]), "=r"((r)[3]) : "r"(addr))

// swizzled offset within a row-major 128B-row tile: row r, 16B-chunk c (0..7)
__device__ __forceinline__ uint32_t swoff(int r, int c) {
    return (uint32_t)(r * 128 + ((c ^ (r & 7)) << 4));
}

enum { EPI_LEAKY02 = 0, EPI_STATS = 1, EPI_TRANS_STATS = 2, EPI_FINAL = 3 };
static constexpr int CONV_SMEM = 3 * 32768 + 256;
static constexpr int OSH_STRIDE = 136;

// ---------------- K1: zero stats + convert weights + transpose -------------
__global__ __launch_bounds__(256) void prep_transpose_kernel(
    const float* __restrict__ w1, const float* __restrict__ pw1,
    const float* __restrict__ pw2, const float* __restrict__ scw,
    const float* __restrict__ mw,
    const float* __restrict__ features, __half* __restrict__ fT)
{
    __shared__ float t[32][33];
    int bid = blockIdx.x;
    if (bid < 4096) {
        int b = bid >> 11;
        int rem = bid & 2047;
        int cB = (rem >> 9) * 32, nB = (rem & 511) * 32;
        int tx = threadIdx.x & 31, ty = threadIdx.x >> 5;
#pragma unroll
        for (int i = 0; i < 4; ++i)
            t[ty + 8 * i][tx] =
                features[((size_t)b * 128 + cB + ty + 8 * i) * Nc + nB + tx];
        __syncthreads();
#pragma unroll
        for (int i = 0; i < 4; ++i)
            fT[((size_t)b * Nc + nB + ty + 8 * i) * 128 + cB + tx] =
                __float2half(t[tx][ty + 8 * i]);
    } else {
        int cb = bid - 4096;  // 0..255
        if (cb == 0) {
            int tt = threadIdx.x;
            if (tt < Bc * 10) g_geoS[tt] = 0.0;
            if (tt < Bc * 55) g_geoG[tt] = 0.0;
            if (tt < Bc * 16) {
                g_p1s[tt] = 0.f; g_p1q[tt] = 0.f;
                g_p2s[tt] = 0.f; g_p2q[tt] = 0.f;
                g_scs[tt] = 0.f; g_scq[tt] = 0.f;
            }
        }
        for (int i = cb * 256 + threadIdx.x; i < WTOT; i += 256 * 256) {
            float v;
            if (i < WOFF_P1) v = w1[i];
            else if (i < WOFF_P2) v = pw1[i - WOFF_P1];
            else if (i < WOFF_SC) v = pw2[i - WOFF_P2];
            else if (i < WOFF_M2) v = scw[i - WOFF_SC];
            else v = mw[i - WOFF_M2];
            g_wh[i] = __float2half(v);
        }
    }
}

// ---------------- geo moments (device body) ----------------
__device__ void geo_body(const float* __restrict__ coords,
                         const int* __restrict__ knn_idx,
                         const float* __restrict__ knn_dist, int bx, int b)
{
    const float* cb = coords + (size_t)b * Nc * 3;
    float S[10];
    float G[55];
#pragma unroll
    for (int c = 0; c < 10; c++) S[c] = 0.f;
#pragma unroll
    for (int p = 0; p < 55; p++) G[p] = 0.f;

    for (int it = bx * 256 + threadIdx.x; it < Nc * Kc; it += 64 * 256) {
        int n = it >> 4;
        size_t base = ((size_t)b * Nc + n) * Kc + (it & 15);
        float cx = cb[n * 3 + 0], cy = cb[n * 3 + 1], cz = cb[n * 3 + 2];
        int j = knn_idx[base];
        float nx = cb[j * 3 + 0], ny = cb[j * 3 + 1], nz = cb[j * 3 + 2];
        float dd = knn_dist[base];
        float g[10] = {cx, cy, cz, nx, ny, nz, cx - nx, cy - ny, cz - nz, dd};
        int p = 0;
#pragma unroll
        for (int c = 0; c < 10; c++) {
            S[c] += g[c];
#pragma unroll
            for (int d = c; d < 10; d++) G[p++] += g[c] * g[d];
        }
    }
#pragma unroll
    for (int c = 0; c < 10; c++)
        for (int off = 16; off; off >>= 1) S[c] += __shfl_xor_sync(~0u, S[c], off);
#pragma unroll
    for (int p = 0; p < 55; p++)
        for (int off = 16; off; off >>= 1) G[p] += __shfl_xor_sync(~0u, G[p], off);
    if ((threadIdx.x & 31) == 0) {
        for (int c = 0; c < 10; c++) atomicAdd(&g_geoS[b * 10 + c], (double)S[c]);
        for (int p = 0; p < 55; p++) atomicAdd(&g_geoG[b * 55 + p], (double)G[p]);
    }
}

// ---------------- closed-form GN stats for BOTH LSE layers -----------------
__global__ void lse_finalize_kernel(
    const float* __restrict__ w1p, const float* __restrict__ b1p,
    const float* __restrict__ gw1, const float* __restrict__ gb1,
    const float* __restrict__ w2p, const float* __restrict__ b2p,
    const float* __restrict__ gw2, const float* __restrict__ gb2,
    float* __restrict__ a1o, float* __restrict__ c1o,
    float* __restrict__ a2o, float* __restrict__ c2o)
{
    int b = blockIdx.x;
    int layer = blockIdx.y;
    const float* w = layer ? w2p : w1p;
    const float* bias = layer ? b2p : b1p;
    const float* gw = layer ? gw2 : gw1;
    const float* gb = layer ? gb2 : gb1;
    float* aOut = layer ? a2o : a1o;
    float* cOut = layer ? c2o : c1o;

    int o = threadIdx.x;  // 128
    float wr[10];
#pragma unroll
    for (int c = 0; c < 10; c++) wr[c] = w[o * 10 + c];
    double t1 = 0.0;
#pragma unroll
    for (int c = 0; c < 10; c++) t1 += (double)wr[c] * g_geoS[b * 10 + c];
    double t2 = 0.0;
    int p = 0;
#pragma unroll
    for (int c = 0; c < 10; c++)
#pragma unroll
        for (int d = c; d < 10; d++) {
            double gv = g_geoG[b * 55 + p]; p++;
            double ww = (double)wr[c] * (double)wr[d];
            t2 += (c == d ? ww : 2.0 * ww) * gv;
        }
    double NK = (double)Nc * (double)Kc;
    double bo = (double)bias[o];
    double sum = t1 + bo * NK;
    double sq  = t2 + 2.0 * bo * t1 + bo * bo * NK;

    __shared__ double gs[16], gq[16];
    if (o < 16) { gs[o] = 0.0; gq[o] = 0.0; }
    __syncthreads();
    atomicAdd(&gs[o >> 3], sum);
    atomicAdd(&gq[o >> 3], sq);
    __syncthreads();
    double M = 8.0 * NK;
    double mean = gs[o >> 3] / M;
    double var = gq[o >> 3] / M - mean * mean;
    if (var < 0.0) var = 0.0;
    double rstd = 1.0 / sqrt(var + 1e-6);
    float a = (float)rstd * gw[o];
    float cs = gb[o] - (float)(mean * rstd) * gw[o];
    aOut[b * 128 + o] = a;
    cOut[b * 128 + o] = cs + (float)bo * a;
}

// ---------------- conv device body: 128n x 128o tile, 64-col K chunks ------
// EPI_FINAL: GN affine for shortcut computed inline from sums (gsum/gsq in).
template <int O, int C, int EPI, int GSIZE>
__device__ __forceinline__ void conv_dev(
    char* smem, int n0, int o0, int b,
    const __half* __restrict__ Wh, const float* __restrict__ bias,
    const __half* __restrict__ in, void* __restrict__ outv,
    const __half* __restrict__ scpre,
    const float* __restrict__ scgw, const float* __restrict__ scgb,
    float* gsum, float* gsq)
{
    const uint32_t sb = smem_u32(smem);
    float* ssh = (float*)(smem + 98304);
    float* sqh = ssh + 16;
    float* osf = (float*)smem;
    __half* osh = (__half*)smem;

    const int tid = threadIdx.x;
    const int w = tid >> 5, lane = tid & 31;
    const int wr = w & 1, wc = w >> 1;
    const int t = lane & 3, g = lane >> 2;

    const __half* xbase = in + ((size_t)b * Nc + n0) * C;
    const __half* wbase = Wh + (size_t)o0 * C;

    uint32_t sOff[4];
    const __half* gxp[4];
    const __half* gwp[4];
#pragma unroll
    for (int i = 0; i < 4; ++i) {
        int id = tid + 256 * i;
        int r = id >> 3, c = id & 7;
        sOff[i] = swoff(r, c);
        gxp[i] = xbase + (size_t)r * C + c * 8;
        gwp[i] = wbase + (size_t)r * C + c * 8;
    }

    const int quad = lane >> 3, lr = lane & 7;
    const int raA = (quad & 1) * 8 + lr, caA = quad >> 1;
    const int raB = (quad >> 1) * 8 + lr, caB = quad & 1;
    uint32_t rbA[4], rxA[4];
#pragma unroll
    for (int mi = 0; mi < 4; ++mi) {
        int row = wr * 64 + mi * 16 + raA;
        rbA[mi] = (uint32_t)(row * 128);
        rxA[mi] = (uint32_t)(row & 7);
    }
    uint32_t rbB[2], rxB[2];
#pragma unroll
    for (int oi = 0; oi < 2; ++oi) {
        int row = wc * 32 + oi * 16 + raB;
        rbB[oi] = 16384u + (uint32_t)(row * 128);
        rxB[oi] = (uint32_t)(row & 7);
    }

    float d[4][4][4];
#pragma unroll
    for (int mi = 0; mi < 4; ++mi)
#pragma unroll
        for (int ni = 0; ni < 4; ++ni)
#pragma unroll
            for (int e = 0; e < 4; ++e) d[mi][ni][e] = 0.f;

    constexpr int NCH = C / 64;
    auto stage = [&](int j) {
        uint32_t base = sb + (uint32_t)(j % 3) * 32768u;
        int cc = j * 64;
#pragma unroll
        for (int i = 0; i < 4; ++i) {
            cpa16(base + sOff[i], gxp[i] + cc);
            cpa16(base + 16384 + sOff[i], gwp[i] + cc);
        }
        CP_COMMIT();
    };
    stage(0);
    if (NCH > 1) stage(1);

    for (int j = 0; j < NCH; ++j) {
        if (j + 1 < NCH) CP_WAIT1(); else CP_WAIT0();
        __syncthreads();
        if (j + 2 < NCH) stage(j + 2);
        const uint32_t base = sb + (uint32_t)(j % 3) * 32768u;
#pragma unroll
        for (int kt = 0; kt < 4; ++kt) {
            uint32_t a[4][4], bb[2][4];
#pragma unroll
            for (int mi = 0; mi < 4; ++mi) {
                uint32_t cA = (uint32_t)(kt * 2 + caA) ^ rxA[mi];
                LDSM4(a[mi], base + rbA[mi] + (cA << 4));
            }
#pragma unroll
            for (int oi = 0; oi < 2; ++oi) {
                uint32_t cB = (uint32_t)(kt * 2 + caB) ^ rxB[oi];
                LDSM4(bb[oi], base + rbB[oi] + (cB << 4));
            }
#pragma unroll
            for (int mi = 0; mi < 4; ++mi)
#pragma unroll
                for (int ni = 0; ni < 4; ++ni) {
                    uint32_t bf[2] = {bb[ni >> 1][(ni & 1) * 2],
                                      bb[ni >> 1][(ni & 1) * 2 + 1]};
                    MMA_F16(d[mi][ni], a[mi], bf);
                }
        }
    }

    // ================= epilogues =================
    if constexpr (EPI == EPI_LEAKY02 || EPI == EPI_STATS) {
        __half* out = (__half*)outv;
        __syncthreads();
        if constexpr (EPI == EPI_STATS) {
            if (tid < 16) { ssh[tid] = 0.f; sqh[tid] = 0.f; }
            __syncthreads();
        }
        float js[4] = {0.f, 0.f, 0.f, 0.f}, jq[4] = {0.f, 0.f, 0.f, 0.f};
#pragma unroll
        for (int mi = 0; mi < 4; ++mi) {
            int p = wr * 64 + mi * 16 + g;
#pragma unroll
            for (int ni = 0; ni < 4; ++ni) {
                int ch = wc * 32 + ni * 8 + 2 * t;
                float b0 = bias[o0 + ch], b1 = bias[o0 + ch + 1];
                float v00 = d[mi][ni][0] + b0, v01 = d[mi][ni][1] + b1;
                float v10 = d[mi][ni][2] + b0, v11 = d[mi][ni][3] + b1;
                if constexpr (EPI == EPI_LEAKY02) {
                    v00 = v00 > 0.f ? v00 : 0.2f * v00;
                    v01 = v01 > 0.f ? v01 : 0.2f * v01;
                    v10 = v10 > 0.f ? v10 : 0.2f * v10;
                    v11 = v11 > 0.f ? v11 : 0.2f * v11;
                } else {
                    js[ni] += v00 + v01 + v10 + v11;
                    jq[ni] += v00 * v00 + v01 * v01 + v10 * v10 + v11 * v11;
                }
                *(__half2*)&osh[p * OSH_STRIDE + ch] = __floats2half2_rn(v00, v01);
                *(__half2*)&osh[(p + 8) * OSH_STRIDE + ch] = __floats2half2_rn(v10, v11);
            }
        }
        if constexpr (EPI == EPI_STATS) {
#pragma unroll
            for (int ni = 0; ni < 4; ++ni) {
                int gl = (wc * 32 + ni * 8) / GSIZE;
                atomicAdd(&ssh[gl], js[ni]);
                atomicAdd(&sqh[gl], jq[ni]);
            }
        }
        __syncthreads();
#pragma unroll
        for (int i = 0; i < 8; ++i) {
            int id = tid + 256 * i;
            int row = id >> 4, c16 = id & 15;
            uint4 v = *(uint4*)&osh[row * OSH_STRIDE + c16 * 8];
            *(uint4*)&out[((size_t)b * Nc + n0 + row) * O + o0 + c16 * 8] = v;
        }
        if constexpr (EPI == EPI_STATS) {
            constexpr int NG = 128 / GSIZE;
            if (tid < NG) {
                atomicAdd(&gsum[b * 16 + o0 / GSIZE + tid], ssh[tid]);
                atomicAdd(&gsq[b * 16 + o0 / GSIZE + tid], sqh[tid]);
            }
        }
    } else {
        __syncthreads();
        if (tid < 16) { ssh[tid] = 0.f; sqh[tid] = 0.f; }
        __syncthreads();
#pragma unroll
        for (int p = 0; p < 2; ++p) {
            if ((wc >> 1) == p) {
                float js[4] = {0.f, 0.f, 0.f, 0.f}, jq[4] = {0.f, 0.f, 0.f, 0.f};
#pragma unroll
                for (int mi = 0; mi < 4; ++mi) {
                    int nr = wr * 64 + mi * 16 + g;
#pragma unroll
                    for (int ni = 0; ni < 4; ++ni) {
                        int oc = (wc & 1) * 32 + ni * 8 + 2 * t;
                        float b0 = 0.f, b1 = 0.f;
                        if constexpr (EPI == EPI_TRANS_STATS) {
                            b0 = bias[o0 + p * 64 + oc];
                            b1 = bias[o0 + p * 64 + oc + 1];
                        }
                        float v00 = d[mi][ni][0] + b0, v01 = d[mi][ni][1] + b1;
                        float v10 = d[mi][ni][2] + b0, v11 = d[mi][ni][3] + b1;
                        if constexpr (EPI == EPI_TRANS_STATS) {
                            js[ni] += v00 + v01 + v10 + v11;
                            jq[ni] += v00 * v00 + v01 * v01 + v10 * v10 + v11 * v11;
                        }
                        osf[oc * 132 + nr] = v00;
                        osf[(oc + 1) * 132 + nr] = v01;
                        osf[oc * 132 + nr + 8] = v10;
                        osf[(oc + 1) * 132 + nr + 8] = v11;
                    }
                }
                if constexpr (EPI == EPI_TRANS_STATS) {
#pragma unroll
                    for (int ni = 0; ni < 4; ++ni) {
                        int gl = (p * 64 + (wc & 1) * 32 + ni * 8) / GSIZE;
                        atomicAdd(&ssh[gl], js[ni]);
                        atomicAdd(&sqh[gl], jq[ni]);
                    }
                }
            }
            __syncthreads();
#pragma unroll
            for (int rr = 0; rr < 8; ++rr) {
                int r = w + rr * 8;
                int og = o0 + p * 64 + r;
                float4 v = *(float4*)&osf[r * 132 + lane * 4];
                if constexpr (EPI == EPI_FINAL) {
                    float* op = (float*)outv + ((size_t)b * O + og) * Nc + n0;
                    float bi = bias[og];
                    // inline shortcut GN affine from sums
                    const float Minv = 1.f / (GSIZE * (float)Nc);
                    int gg = og / GSIZE;
                    float mean = gsum[b * 16 + gg] * Minv;
                    float var = fmaxf(gsq[b * 16 + gg] * Minv - mean * mean, 0.f);
                    float rstd = rsqrtf(var + 1e-6f);
                    float av = rstd * scgw[og];
                    float cv = scgb[og] - mean * av;
                    uint2 sraw = *(const uint2*)(scpre +
                        ((size_t)b * O + og) * Nc + n0 + lane * 4);
                    float2 s0 = __half22float2(*(__half2*)&sraw.x);
                    float2 s1 = __half22float2(*(__half2*)&sraw.y);
                    float ss[4] = {s0.x, s0.y, s1.x, s1.y};
                    float4 rrv;
#pragma unroll
                    for (int e = 0; e < 4; ++e) {
                        float x = (&v.x)[e] + bi + fmaf(ss[e], av, cv);
                        (&rrv.x)[e] = x > 0.f ? x : 0.01f * x;
                    }
                    *(float4*)(op + lane * 4) = rrv;
                } else {
                    __half* op = (__half*)outv + ((size_t)b * O + og) * Nc + n0;
                    uint2 st;
                    *(__half2*)&st.x = __floats2half2_rn(v.x, v.y);
                    *(__half2*)&st.y = __floats2half2_rn(v.z, v.w);
                    *(uint2*)(op + lane * 4) = st;
                }
            }
            __syncthreads();
        }
        if constexpr (EPI == EPI_TRANS_STATS) {
            constexpr int NG = 128 / GSIZE;
            if (tid < NG) {
                atomicAdd(&gsum[b * 16 + o0 / GSIZE + tid], ssh[tid]);
                atomicAdd(&gsq[b * 16 + o0 / GSIZE + tid], sqh[tid]);
            }
        }
    }
}

// ---------------- standalone conv kernels ----------------------------------
template <int O, int C, int EPI, int GSIZE>
__global__ __launch_bounds__(256, 2) void mma_conv_k(
    const __half* __restrict__ Wh, const float* __restrict__ bias,
    const __half* __restrict__ in, void* __restrict__ outv,
    const __half* __restrict__ scpre,
    const float* __restrict__ scgw, const float* __restrict__ scgb,
    float* gsum, float* gsq)
{
    extern __shared__ __align__(16) char smem[];
    conv_dev<O, C, EPI, GSIZE>(smem, blockIdx.x * 128, blockIdx.y * 128,
                               blockIdx.z, Wh, bias, in, outv,
                               scpre, scgw, scgb, gsum, gsq);
}

// ---------------- K2: mlp1 + shortcut conv + geo moments -------------------
__global__ __launch_bounds__(256, 2) void fused_a_kernel(
    const __half* __restrict__ wh, const float* __restrict__ b1,
    const float* __restrict__ sc_b, const __half* __restrict__ fT,
    __half* __restrict__ x1, __half* __restrict__ scp,
    float* scs, float* scq,
    const float* __restrict__ coords, const int* __restrict__ knn_idx,
    const float* __restrict__ knn_dist)
{
    extern __shared__ __align__(16) char smem[];
    int y = blockIdx.y, b = blockIdx.z;
    if (y == 5) {
        if (blockIdx.x < 64) geo_body(coords, knn_idx, knn_dist, blockIdx.x, b);
        return;
    }
    if (y == 0)
        conv_dev<128, 128, EPI_LEAKY02, 8>(smem, blockIdx.x * 128, 0, b,
            wh + WOFF_W1, b1, fT, x1, nullptr, nullptr, nullptr, nullptr, nullptr);
    else
        conv_dev<512, 128, EPI_TRANS_STATS, 32>(smem, blockIdx.x * 128,
            (y - 1) * 128, b, wh + WOFF_SC, sc_b, fT, scp,
            nullptr, nullptr, nullptr, scs, scq);
}

// ---------------- normalize p2 -> x3 with inline fin2 ----------------------
__global__ __launch_bounds__(256) void normalize_h_kernel(
    const __half* __restrict__ p, __half* __restrict__ x,
    const float* __restrict__ sums, const float* __restrict__ sqs,
    const float* __restrict__ gw, const float* __restrict__ gb)
{
    size_t i = ((size_t)blockIdx.x * blockDim.x + threadIdx.x) * 4;
    int c = (int)(i % 256);
    int b = (int)(i / ((size_t)Nc * 256));
    const float Minv = 1.f / (16.f * Nc);
    int g = c >> 4;
    float mean = sums[b * 16 + g] * Minv;
    float var = fmaxf(sqs[b * 16 + g] * Minv - mean * mean, 0.f);
    float rstd = rsqrtf(var + 1e-6f);
    __half2 v0 = *(const __half2*)(p + i);
    __half2 v1 = *(const __half2*)(p + i + 2);
    float vv[4] = {__half2float(v0.x), __half2float(v0.y),
                   __half2float(v1.x), __half2float(v1.y)};
    float rr[4];
#pragma unroll
    for (int e = 0; e < 4; ++e) {
        float a = rstd * gw[c + e];
        float cc = gb[c + e] - mean * a;
        rr[e] = fmaxf(fmaf(vv[e], a, cc), 0.f);
    }
    *(__half2*)(x + i) = __floats2half2_rn(rr[0], rr[1]);
    *(__half2*)(x + i + 2) = __floats2half2_rn(rr[2], rr[3]);
}

// ---------------- fused LSE (AFF path derives affine from sums inline) -----
static constexpr int PTS = 8;
template <bool AFF>
__global__ __launch_bounds__(128) void lse_apply_kernel(
    const float* __restrict__ coords, const int* __restrict__ knn_idx,
    const float* __restrict__ knn_dist, const float* __restrict__ w,
    const float* __restrict__ aArr, const float* __restrict__ cArr,
    const __half* __restrict__ xsrc, __half* __restrict__ mout,
    const float* __restrict__ sums, const float* __restrict__ sqs,
    const float* __restrict__ pgw, const float* __restrict__ pgb)
{
    __shared__ int sh_idx[PTS * 16];
    __shared__ float sh_nbr[PTS * 16][3];
    __shared__ float sh_dist[PTS * 16];
    __shared__ float sh_ctr[PTS][3];
    __shared__ float2 spart[PTS][64];

    const int b = blockIdx.y;
    const int n0 = blockIdx.x * PTS;
    const int tid = threadIdx.x;
    const float* cb = coords + (size_t)b * Nc * 3;

    if (tid < PTS * 16) {
        size_t base = ((size_t)b * Nc + n0) * 16 + tid;
        sh_idx[tid] = knn_idx[base];
        sh_dist[tid] = knn_dist[base];
    }
    if (tid < PTS * 3) sh_ctr[tid / 3][tid % 3] = cb[n0 * 3 + tid];
    __syncthreads();
    if (tid < PTS * 16) {
        int j = sh_idx[tid];
        sh_nbr[tid][0] = cb[j * 3 + 0];
        sh_nbr[tid][1] = cb[j * 3 + 1];
        sh_nbr[tid][2] = cb[j * 3 + 2];
    }
    float w0 = w[tid * 10 + 0], w1 = w[tid * 10 + 1], w2 = w[tid * 10 + 2];
    float w3 = w[tid * 10 + 3], w4 = w[tid * 10 + 4], w5 = w[tid * 10 + 5];
    float w6 = w[tid * 10 + 6], w7 = w[tid * 10 + 7], w8 = w[tid * 10 + 8];
    float wd = w[tid * 10 + 9];
    const float wcx = w0 + w6, wcy = w1 + w7, wcz = w2 + w8;
    const float wnx = w3 - w6, wny = w4 - w7, wnz = w5 - w8;
    const float a = aArr[b * 128 + tid];
    const float cc = cArr[b * 128 + tid];

    const int cp = tid & 63, h = tid >> 6;
    float an0 = 0.f, an1 = 0.f, cn0 = 0.f, cn1 = 0.f;
    if (AFF) {
        // inline pool1 GN finalize (gsize=8, Cc=128)
        const float Minv = 1.f / (8.f * Nc);
        int ch0 = 2 * cp;
        int g = ch0 >> 3;
        float mean = sums[b * 16 + g] * Minv;
        float var = fmaxf(sqs[b * 16 + g] * Minv - mean * mean, 0.f);
        float rstd = rsqrtf(var + 1e-6f);
        an0 = rstd * pgw[ch0];
        cn0 = pgb[ch0] - mean * an0;
        an1 = rstd * pgw[ch0 + 1];
        cn1 = pgb[ch0 + 1] - mean * an1;
    }
    const __half* xb = xsrc + (size_t)b * Nc * 128;
    __syncthreads();

    float2 accn[PTS];
#pragma unroll
    for (int pi = 0; pi < PTS; pi++) {
        float cx = sh_ctr[pi][0], cy = sh_ctr[pi][1], cz = sh_ctr[pi][2];
        float dotc = wcx * cx + wcy * cy + wcz * cz;
        float accg = 0.f;
#pragma unroll
        for (int k = 0; k < 16; k++) {
            int s = pi * 16 + k;
            float dot = dotc + wnx * sh_nbr[s][0] + wny * sh_nbr[s][1] +
                        wnz * sh_nbr[s][2] + wd * sh_dist[s];
            accg += fmaxf(fmaf(dot, a, cc), 0.f);
        }
        mout[((size_t)b * Nc + n0 + pi) * 256 + tid] = __float2half(accg * 0.0625f);

        float2 acc = make_float2(0.f, 0.f);
#pragma unroll
        for (int k = 0; k < 8; k++) {
            int s = pi * 16 + h * 8 + k;
            int j = sh_idx[s];
            float2 f = __half22float2(*(const __half2*)&xb[(size_t)j * 128 + 2 * cp]);
            if (AFF) {
                f.x = fmaxf(fmaf(f.x, an0, cn0), 0.f);
                f.y = fmaxf(fmaf(f.y, an1, cn1), 0.f);
            }
            acc.x += f.x; acc.y += f.y;
        }
        if (h == 1) spart[pi][cp] = acc;
        accn[pi] = acc;
    }
    __syncthreads();
    if (h == 0) {
#pragma unroll
        for (int pi = 0; pi < PTS; pi++) {
            float2 o = spart[pi][cp];
            o.x = (o.x + accn[pi].x) * 0.0625f;
            o.y = (o.y + accn[pi].y) * 0.0625f;
            *(__half2*)&mout[((size_t)b * Nc + n0 + pi) * 256 + 128 + 2 * cp] =
                __floats2half2_rn(o.x, o.y);
        }
    }
}

// ---------------- host ----------------
#define SYM(ty, p, s) do { void* _t; cudaGetSymbolAddress(&_t, s); p = (ty)_t; } while (0)

extern "C" void kernel_launch(void* const* d_in, const int* in_sizes, int n_in,
                              void* d_out, int out_size)
{
    (void)in_sizes; (void)n_in; (void)out_size;
    const float* coords   = (const float*)d_in[0];
    const float* features = (const float*)d_in[1];
    const float* knn_dist = (const float*)d_in[2];
    const int*   knn_idx  = (const int*)d_in[3];
    const float* w1       = (const float*)d_in[4];
    const float* b1       = (const float*)d_in[5];
    const float* lse1_w   = (const float*)d_in[6];
    const float* lse1_b   = (const float*)d_in[7];
    const float* lse1_gw  = (const float*)d_in[8];
    const float* lse1_gb  = (const float*)d_in[9];
    const float* pool1_w  = (const float*)d_in[10];
    const float* pool1_b  = (const float*)d_in[11];
    const float* pool1_gw = (const float*)d_in[12];
    const float* pool1_gb = (const float*)d_in[13];
    const float* lse2_w   = (const float*)d_in[14];
    const float* lse2_b   = (const float*)d_in[15];
    const float* lse2_gw  = (const float*)d_in[16];
    const float* lse2_gb  = (const float*)d_in[17];
    const float* pool2_w  = (const float*)d_in[18];
    const float* pool2_b  = (const float*)d_in[19];
    const float* pool2_gw = (const float*)d_in[20];
    const float* pool2_gb = (const float*)d_in[21];
    const float* mlp2_w   = (const float*)d_in[22];
    const float* mlp2_b   = (const float*)d_in[23];
    const float* sc_w     = (const float*)d_in[24];
    const float* sc_b     = (const float*)d_in[25];
    const float* sc_gw    = (const float*)d_in[26];
    const float* sc_gb    = (const float*)d_in[27];
    float* out = (float*)d_out;

    __half *fT, *wh, *x1, *m1, *p1, *m2, *p2, *x3, *scp;
    float *l1a, *l1c, *l2a, *l2c;
    float *p1s, *p1q, *p2s, *p2q, *scs, *scq;
    SYM(__half*, fT, g_fT); SYM(__half*, wh, g_wh);
    SYM(__half*, x1, g_x1); SYM(__half*, m1, g_m1); SYM(__half*, p1, g_p1);
    SYM(__half*, m2, g_m2); SYM(__half*, p2, g_p2); SYM(__half*, x3, g_x3);
    SYM(__half*, scp, g_scp);
    SYM(float*, l1a, g_lse1a); SYM(float*, l1c, g_lse1c);
    SYM(float*, l2a, g_lse2a); SYM(float*, l2c, g_lse2c);
    SYM(float*, p1s, g_p1s); SYM(float*, p1q, g_p1q);
    SYM(float*, p2s, g_p2s); SYM(float*, p2q, g_p2q);
    SYM(float*, scs, g_scs); SYM(float*, scq, g_scq);

    cudaFuncSetAttribute(fused_a_kernel,
                         cudaFuncAttributeMaxDynamicSharedMemorySize, CONV_SMEM);
    cudaFuncSetAttribute(mma_conv_k<128, 256, EPI_STATS, 8>,
                         cudaFuncAttributeMaxDynamicSharedMemorySize, CONV_SMEM);
    cudaFuncSetAttribute(mma_conv_k<256, 256, EPI_STATS, 16>,
                         cudaFuncAttributeMaxDynamicSharedMemorySize, CONV_SMEM);
    cudaFuncSetAttribute(mma_conv_k<512, 256, EPI_FINAL, 32>,
                         cudaFuncAttributeMaxDynamicSharedMemorySize, CONV_SMEM);

    // K1: zero stats + weight convert + feature transpose
    prep_transpose_kernel<<<4096 + 256, 256>>>(w1, pool1_w, pool2_w, sc_w,
                                               mlp2_w, features, fT);
    // K2: mlp1 (y=0) + shortcut conv (y=1..4) + geo moments (y=5)
    fused_a_kernel<<<dim3(Nc / 128, 6, Bc), 256, CONV_SMEM>>>(
        wh, b1, sc_b, fT, x1, scp, scs, scq, coords, knn_idx, knn_dist);
    // K3: closed-form GN for both LSE layers
    lse_finalize_kernel<<<dim3(Bc, 2), 128>>>(lse1_w, lse1_b, lse1_gw, lse1_gb,
                                              lse2_w, lse2_b, lse2_gw, lse2_gb,
                                              l1a, l1c, l2a, l2c);
    // K4: lse1
    lse_apply_kernel<false><<<dim3(Nc / PTS, Bc), 128>>>(
        coords, knn_idx, knn_dist, lse1_w, l1a, l1c, x1, m1,
        nullptr, nullptr, nullptr, nullptr);
    // K5: pool1 conv + stats
    mma_conv_k<128, 256, EPI_STATS, 8>
        <<<dim3(Nc / 128, 1, Bc), 256, CONV_SMEM>>>(wh + WOFF_P1, pool1_b, m1, p1,
                                                    nullptr, nullptr, nullptr,
                                                    p1s, p1q);
    // K6: lse2 (inline pool1 GN finalize)
    lse_apply_kernel<true><<<dim3(Nc / PTS, Bc), 128>>>(
        coords, knn_idx, knn_dist, lse2_w, l2a, l2c, p1, m2,
        p1s, p1q, pool1_gw, pool1_gb);
    // K7: pool2 conv + stats
    mma_conv_k<256, 256, EPI_STATS, 16>
        <<<dim3(Nc / 128, 2, Bc), 256, CONV_SMEM>>>(wh + WOFF_P2, pool2_b, m2, p2,
                                                    nullptr, nullptr, nullptr,
                                                    p2s, p2q);
    // K8: normalize (inline pool2 GN finalize)
    normalize_h_kernel<<<(Bc * Nc * 256) / 1024, 256>>>(p2, x3, p2s, p2q,
                                                        pool2_gw, pool2_gb);
    // K9: final conv + inline shortcut GN + leaky(0.01) -> out [b][o][n] fp32
    mma_conv_k<512, 256, EPI_FINAL, 32>
        <<<dim3(Nc / 128, 4, Bc), 256, CONV_SMEM>>>(wh + WOFF_M2, mlp2_b, x3, out,
                                                    scp, sc_gw, sc_gb, scs, scq);
}